// round 2
// baseline (speedup 1.0000x reference)
#include <cuda_runtime.h>
#include <math.h>

typedef unsigned long long ull;

#define T_   64
#define B_   32
#define H_   256
#define G_   768     // 3*H
#define DD_  256
#define DIN_ 4096
#define DOUT_ 942
#define M_   (T_*B_) // 2048

// ---------------- device scratch (static; no allocations) ----------------
__device__ float g_day [M_*DD_];          // day embedding
__device__ float g_gif [M_*G_];           // input-gates fwd
__device__ float g_gir [M_*G_];           // input-gates rev
__device__ float g_hf  [B_*H_];           // fwd hidden state
__device__ float g_hrev[T_*B_*H_];        // 64 rev chain states
__device__ float g_fwd [T_*B_*H_];        // fwd outputs [t][b][h]
__device__ float g_rev [T_*T_*B_*H_];     // rev outputs [i][t][b][h] (t<=i valid)  134MB
__device__ float g_gh  [65*B_*G_];        // per-step recurrent gates scratch
__device__ float g_sc  [T_*T_*B_];        // scores / alpha [i][t][b]
__device__ float g_ht  [M_*4*H_];         // concat features [i*B+b][1024]
__device__ float g_hto [M_*DD_];          // pre-output

// ---------------- math helpers ----------------
__device__ __forceinline__ ull splat2(float x) {
    ull r; asm("mov.b64 %0,{%1,%1};" : "=l"(r) : "f"(x)); return r;
}
__device__ __forceinline__ void fma2(ull& c, ull a, ull b) {
    asm("fma.rn.f32x2 %0,%1,%2,%0;" : "+l"(c) : "l"(a), "l"(b));
}
__device__ __forceinline__ float2 unpack2(ull v) {
    float2 r; asm("mov.b64 {%0,%1},%2;" : "=f"(r.x), "=f"(r.y) : "l"(v)); return r;
}
__device__ __forceinline__ float ex2f_(float x) {
    float y; asm("ex2.approx.f32 %0,%1;" : "=f"(y) : "f"(x)); return y;
}
__device__ __forceinline__ float rcpf_(float x) {
    float y; asm("rcp.approx.f32 %0,%1;" : "=f"(y) : "f"(x)); return y;
}
__device__ __forceinline__ float sigm(float x) {
    return rcpf_(1.f + ex2f_(-1.4426950408889634f * x));
}
__device__ __forceinline__ float tanh_(float x) {
    return fmaf(-2.f, rcpf_(1.f + ex2f_(2.8853900817779268f * x)), 1.f);
}

// ---------------- init ----------------
__global__ void zero_state() {
    int idx = blockIdx.x * 256 + threadIdx.x;
    if (idx < T_*B_*H_) g_hrev[idx] = 0.f;
    if (idx < B_*H_)    g_hf[idx]   = 0.f;
}

// ---------------- generic GEMM: C[M,N] = A[M,K] @ B[N,K]^T + bias ----------------
// 128 threads, tile 32 rows x 64 cols, K chunked by 16, f32x2 inner.
template<bool SIG>
__global__ __launch_bounds__(128) void gemm_nt(
    const float* __restrict__ A, const float* __restrict__ Bm,
    const float* __restrict__ bias, float* __restrict__ C,
    int M, int N, int K)
{
    __shared__ float As[16*36];  // [k][row], pad 36
    __shared__ float Bs[16*68];  // [k][col], pad 68
    const int tid = threadIdx.x;
    const int m0 = blockIdx.y * 32;
    const int n0 = blockIdx.x * 64;

    const int lrow = tid & 31;          // A load: row (lane-fast)
    const int lkq  = (tid >> 5) * 4;    // A load: k quad
    const int tm = tid >> 5;            // 0..3  -> rows tm*8..+7
    const int tn = tid & 31;            // cols tn*2..+1

    ull acc[8];
#pragma unroll
    for (int r = 0; r < 8; r++) acc[r] = 0ull;

    for (int k0 = 0; k0 < K; k0 += 16) {
        // stage A (32x16): uncoalesced LDG, conflict-free STS
        float4 av = *(const float4*)(A + (size_t)(m0 + lrow) * K + k0 + lkq);
        // stage B (64x16): coalesced LDG, bounds-guarded
        float4 bv[2];
#pragma unroll
        for (int rr = 0; rr < 2; rr++) {
            int j  = rr * 32 + (tid >> 2);
            int kq = (tid & 3) * 4;
            int gn = n0 + j;
            bv[rr] = (gn < N) ? *(const float4*)(Bm + (size_t)gn * K + k0 + kq)
                              : make_float4(0.f, 0.f, 0.f, 0.f);
        }
        __syncthreads();
        As[(lkq+0)*36 + lrow] = av.x;
        As[(lkq+1)*36 + lrow] = av.y;
        As[(lkq+2)*36 + lrow] = av.z;
        As[(lkq+3)*36 + lrow] = av.w;
#pragma unroll
        for (int rr = 0; rr < 2; rr++) {
            int j  = rr * 32 + (tid >> 2);
            int kq = (tid & 3) * 4;
            Bs[(kq+0)*68 + j] = bv[rr].x;
            Bs[(kq+1)*68 + j] = bv[rr].y;
            Bs[(kq+2)*68 + j] = bv[rr].z;
            Bs[(kq+3)*68 + j] = bv[rr].w;
        }
        __syncthreads();
#pragma unroll
        for (int kk = 0; kk < 16; kk++) {
            float4 a0 = *(const float4*)&As[kk*36 + tm*8];
            float4 a1 = *(const float4*)&As[kk*36 + tm*8 + 4];
            ull b = *(const ull*)&Bs[kk*68 + tn*2];
            fma2(acc[0], splat2(a0.x), b);
            fma2(acc[1], splat2(a0.y), b);
            fma2(acc[2], splat2(a0.z), b);
            fma2(acc[3], splat2(a0.w), b);
            fma2(acc[4], splat2(a1.x), b);
            fma2(acc[5], splat2(a1.y), b);
            fma2(acc[6], splat2(a1.z), b);
            fma2(acc[7], splat2(a1.w), b);
        }
    }

    const int col = n0 + tn * 2;
#pragma unroll
    for (int r = 0; r < 8; r++) {
        int row = m0 + tm * 8 + r;
        float2 v = unpack2(acc[r]);
        if (col + 2 <= N) {
            v.x += bias[col];
            v.y += bias[col + 1];
            if (SIG) { v.x = sigm(v.x); v.y = sigm(v.y); }
            *(float2*)(C + (size_t)row * N + col) = v;
        } else if (col < N) {
            v.x += bias[col];
            if (SIG) v.x = sigm(v.x);
            C[(size_t)row * N + col] = v.x;
        }
    }
}

// ---------------- per-step recurrent GEMM: gh = h @ Whh^T + bhh ----------------
// grid (6 col-tiles of 128, ntasks). Task y<64-s -> rev chain i=s+y; y==64-s -> fwd.
__global__ __launch_bounds__(128) void step_gemm(
    const float* __restrict__ Whh_f, const float* __restrict__ Whh_r,
    const float* __restrict__ bhh_f, const float* __restrict__ bhh_r, int s)
{
    __shared__ float Hs[256*36];   // [k][b]
    __shared__ float Ws[16*132];   // [k][j]
    const int tid = threadIdx.x;
    const int y = blockIdx.y;
    const bool isf = (y == T_ - s);
    const int i = s + y;
    const float* hsrc = isf ? g_hf : (g_hrev + (size_t)i * (B_*H_));
    const float* W    = isf ? Whh_f : Whh_r;
    const float* bias = isf ? bhh_f : bhh_r;
    const int j0 = blockIdx.x * 128;

    // load full h (32x256) transposed: conflict-free STS
    {
        int b  = tid & 31;
        int kg = tid >> 5;
#pragma unroll
        for (int r = 0; r < 16; r++) {
            int k = r * 16 + kg * 4;
            float4 v = *(const float4*)(hsrc + b * 256 + k);
            Hs[(k+0)*36 + b] = v.x;
            Hs[(k+1)*36 + b] = v.y;
            Hs[(k+2)*36 + b] = v.z;
            Hs[(k+3)*36 + b] = v.w;
        }
    }

    const int tm = tid >> 5;   // rows tm*8..+7
    const int tn = tid & 31;   // cols tn*4..+3
    ull acc[8][2];
#pragma unroll
    for (int r = 0; r < 8; r++) { acc[r][0] = 0ull; acc[r][1] = 0ull; }

    for (int k0 = 0; k0 < 256; k0 += 16) {
        __syncthreads();
#pragma unroll
        for (int rr = 0; rr < 4; rr++) {
            int j  = rr * 32 + (tid >> 2);
            int kq = (tid & 3) * 4;
            float4 v = *(const float4*)(W + (size_t)(j0 + j) * 256 + k0 + kq);
            Ws[(kq+0)*132 + j] = v.x;
            Ws[(kq+1)*132 + j] = v.y;
            Ws[(kq+2)*132 + j] = v.z;
            Ws[(kq+3)*132 + j] = v.w;
        }
        __syncthreads();
#pragma unroll
        for (int kk = 0; kk < 16; kk++) {
            int k = k0 + kk;
            float4 a0 = *(const float4*)&Hs[k*36 + tm*8];
            float4 a1 = *(const float4*)&Hs[k*36 + tm*8 + 4];
            ulonglong2 bq = *(const ulonglong2*)&Ws[kk*132 + tn*4];
            fma2(acc[0][0], splat2(a0.x), bq.x); fma2(acc[0][1], splat2(a0.x), bq.y);
            fma2(acc[1][0], splat2(a0.y), bq.x); fma2(acc[1][1], splat2(a0.y), bq.y);
            fma2(acc[2][0], splat2(a0.z), bq.x); fma2(acc[2][1], splat2(a0.z), bq.y);
            fma2(acc[3][0], splat2(a0.w), bq.x); fma2(acc[3][1], splat2(a0.w), bq.y);
            fma2(acc[4][0], splat2(a1.x), bq.x); fma2(acc[4][1], splat2(a1.x), bq.y);
            fma2(acc[5][0], splat2(a1.y), bq.x); fma2(acc[5][1], splat2(a1.y), bq.y);
            fma2(acc[6][0], splat2(a1.z), bq.x); fma2(acc[6][1], splat2(a1.z), bq.y);
            fma2(acc[7][0], splat2(a1.w), bq.x); fma2(acc[7][1], splat2(a1.w), bq.y);
        }
    }

    const int col = j0 + tn * 4;
    float b0 = bias[col], b1 = bias[col+1], b2 = bias[col+2], b3 = bias[col+3];
#pragma unroll
    for (int r = 0; r < 8; r++) {
        int row = tm * 8 + r;
        float* dst = g_gh + (size_t)(y * 32 + row) * G_ + col;
        float2 v0 = unpack2(acc[r][0]); v0.x += b0; v0.y += b1;
        float2 v1 = unpack2(acc[r][1]); v1.x += b2; v1.y += b3;
        *(float2*)dst = v0;
        *(float2*)(dst + 2) = v1;
    }
}

// ---------------- per-step GRU pointwise ----------------
// grid (ntasks, 4): block handles 8 batch rows; 256 threads = h.
__global__ __launch_bounds__(256) void gru_elt(int s) {
    const int y = blockIdx.x;
    const bool isf = (y == T_ - s);
    const int i = s + y;
    const int h = threadIdx.x;
    const int b0 = blockIdx.y * 8;
    const float* gi_base = isf ? (g_gif + (size_t)s * B_ * G_)
                               : (g_gir + (size_t)(i - s) * B_ * G_);
    const float* gh_base = g_gh + (size_t)y * B_ * G_;
    float* hstate = isf ? g_hf : (g_hrev + (size_t)i * (B_*H_));
    float* outp   = isf ? (g_fwd + (size_t)s * (B_*H_))
                        : (g_rev + ((size_t)i * 64 + s) * (B_*H_));
#pragma unroll
    for (int bb = 0; bb < 8; bb++) {
        int b = b0 + bb;
        const float* gi = gi_base + (size_t)b * G_;
        const float* gh = gh_base + (size_t)b * G_;
        float hprev = hstate[b*256 + h];
        float r = sigm(gi[h]       + gh[h]);
        float z = sigm(gi[256 + h] + gh[256 + h]);
        float n = tanh_(gi[512 + h] + r * gh[512 + h]);
        float hn = (1.f - z) * n + z * hprev;
        hstate[b*256 + h] = hn;
        outp[b*256 + h]   = hn;
    }
}

// ---------------- attention scores ----------------
__global__ __launch_bounds__(256) void scores_k(
    const float* __restrict__ attn_w, const float* __restrict__ attn_b)
{
    const int i = blockIdx.x;
    const int w = threadIdx.x >> 5, l = threadIdx.x & 31;
    __shared__ float wf[256], wr[256];
    wf[threadIdx.x] = attn_w[threadIdx.x];
    wr[threadIdx.x] = attn_w[256 + threadIdx.x];
    __syncthreads();
    float ab = attn_b[0];
    for (int t = 0; t <= i; t++) {
#pragma unroll
        for (int bb = 0; bb < 4; bb++) {
            int b = w * 4 + bb;
            const float* fp = g_fwd + ((size_t)(t*32 + b)) * 256 + l*8;
            const float* rp = g_rev + ((size_t)((i*64 + t)*32 + b)) * 256 + l*8;
            float acc = 0.f;
#pragma unroll
            for (int q = 0; q < 8; q++)
                acc += fp[q]*wf[l*8+q] + rp[q]*wr[l*8+q];
#pragma unroll
            for (int o = 16; o; o >>= 1) acc += __shfl_xor_sync(0xffffffffu, acc, o);
            if (l == 0) g_sc[(i*64 + t)*32 + b] = acc + ab;
        }
    }
}

__global__ void softmax_k() {
    const int i = blockIdx.x;
    const int b = threadIdx.x;  // 32 threads
    float m = -1e30f;
    for (int t = 0; t <= i; t++) m = fmaxf(m, g_sc[(i*64 + t)*32 + b]);
    float ssum = 0.f;
    for (int t = 0; t <= i; t++) {
        float e = ex2f_(1.4426950408889634f * (g_sc[(i*64 + t)*32 + b] - m));
        g_sc[(i*64 + t)*32 + b] = e;
        ssum += e;
    }
    float inv = 1.f / ssum;
    for (int t = 0; t <= i; t++) g_sc[(i*64 + t)*32 + b] *= inv;
}

// ---------------- context + concat ----------------
__global__ __launch_bounds__(256) void context_k() {
    const int i = blockIdx.x, bg = blockIdx.y;
    const int h = threadIdx.x;
    float accf[8], accr[8];
#pragma unroll
    for (int j = 0; j < 8; j++) { accf[j] = 0.f; accr[j] = 0.f; }
    for (int t = 0; t <= i; t++) {
        const float* al = g_sc + (i*64 + t)*32 + bg*8;
        const float* fr = g_fwd + ((size_t)(t*32 + bg*8)) * 256 + h;
        const float* rr = g_rev + ((size_t)((i*64 + t)*32 + bg*8)) * 256 + h;
#pragma unroll
        for (int j = 0; j < 8; j++) {
            float a = al[j];
            accf[j] += a * fr[(size_t)j*256];
            accr[j] += a * rr[(size_t)j*256];
        }
    }
    float inv = 1.f / (float)(i + 1);
#pragma unroll
    for (int j = 0; j < 8; j++) {
        int b = bg*8 + j;
        size_t row = (size_t)(i*32 + b);
        g_ht[row*1024 + h]       = accf[j] * inv;
        g_ht[row*1024 + 256 + h] = accr[j] * inv;
        g_ht[row*1024 + 512 + h] = g_fwd[((size_t)(i*32 + b))*256 + h];
        g_ht[row*1024 + 768 + h] = g_rev[((size_t)((i*64 + i)*32 + b))*256 + h];
    }
}

// ---------------- launch ----------------
extern "C" void kernel_launch(void* const* d_in, const int* in_sizes, int n_in,
                              void* d_out, int out_size)
{
    const float* x      = (const float*)d_in[0];
    const float* W_emb  = (const float*)d_in[1];
    const float* b_emb  = (const float*)d_in[2];
    const float* Wih_f  = (const float*)d_in[3];
    const float* Whh_f  = (const float*)d_in[4];
    const float* bih_f  = (const float*)d_in[5];
    const float* bhh_f  = (const float*)d_in[6];
    const float* Wih_r  = (const float*)d_in[7];
    const float* Whh_r  = (const float*)d_in[8];
    const float* bih_r  = (const float*)d_in[9];
    const float* bhh_r  = (const float*)d_in[10];
    const float* attn_w = (const float*)d_in[11];
    const float* attn_b = (const float*)d_in[12];
    const float* W_ao   = (const float*)d_in[13];
    const float* b_ao   = (const float*)d_in[14];
    const float* W_o    = (const float*)d_in[15];
    const float* b_o    = (const float*)d_in[16];
    float* out = (float*)d_out;

    void *p_day, *p_gif, *p_gir, *p_ht, *p_hto;
    cudaGetSymbolAddress(&p_day, g_day);
    cudaGetSymbolAddress(&p_gif, g_gif);
    cudaGetSymbolAddress(&p_gir, g_gir);
    cudaGetSymbolAddress(&p_ht,  g_ht);
    cudaGetSymbolAddress(&p_hto, g_hto);

    zero_state<<<2048, 256>>>();

    // day_emb = x @ W_emb^T + b_emb   (2048 x 256, K=4096)
    gemm_nt<false><<<dim3(4, 64), 128>>>(x, W_emb, b_emb, (float*)p_day, M_, DD_, DIN_);
    // gi_f / gi_r = day_emb @ Wih^T + bih   (2048 x 768, K=256)
    gemm_nt<false><<<dim3(12, 64), 128>>>((const float*)p_day, Wih_f, bih_f, (float*)p_gif, M_, G_, DD_);
    gemm_nt<false><<<dim3(12, 64), 128>>>((const float*)p_day, Wih_r, bih_r, (float*)p_gir, M_, G_, DD_);

    // lockstep recurrence: 64 steps, ntasks = (64-s) rev chains + 1 fwd
    for (int s = 0; s < 64; s++) {
        int ntasks = 65 - s;
        step_gemm<<<dim3(6, ntasks), 128>>>(Whh_f, Whh_r, bhh_f, bhh_r, s);
        gru_elt<<<dim3(ntasks, 4), 256>>>(s);
    }

    scores_k<<<64, 256>>>(attn_w, attn_b);
    softmax_k<<<64, 32>>>();
    context_k<<<dim3(64, 4), 256>>>();

    // h_t_out = h_t @ W_ao^T + b_ao   (2048 x 256, K=1024)
    gemm_nt<false><<<dim3(4, 64), 128>>>((const float*)p_ht, W_ao, b_ao, (float*)p_hto, M_, DD_, 4*H_);
    // out = sigmoid(h_t_out @ W_o^T + b_o)   (2048 x 942, K=256)
    gemm_nt<true><<<dim3(15, 64), 128>>>((const float*)p_hto, W_o, b_o, out, M_, DOUT_, DD_);
}

// round 3
// speedup vs baseline: 1.0127x; 1.0127x over previous
#include <cuda_runtime.h>
#include <math.h>

typedef unsigned long long ull;

#define T_   64
#define B_   32
#define H_   256
#define G_   768
#define DD_  256
#define DIN_ 4096
#define DOUT_ 942
#define M_   (T_*B_)

#define NCHUNK 8
#define SLOTS  18
#define NBLK   (NCHUNK*SLOTS)   // 144 blocks, 1 per SM

// ---------------- device scratch (static; no allocations) ----------------
__device__ float g_day [M_*DD_];
__device__ float g_gif [M_*G_];
__device__ float g_gir [M_*G_];
__device__ float g_hf  [B_*H_];
__device__ float g_hrev[T_*B_*H_];
__device__ float g_fwd [T_*B_*H_];
__device__ float g_rev [T_*T_*B_*H_];     // [i][t][b][h], t<=i valid
__device__ float g_sc  [T_*T_*B_];
__device__ float g_ht  [M_*4*H_];
__device__ float g_hto [M_*DD_];
__device__ unsigned int g_bar;

// ---------------- math helpers ----------------
__device__ __forceinline__ ull splat2(float x) {
    ull r; asm("mov.b64 %0,{%1,%1};" : "=l"(r) : "f"(x)); return r;
}
__device__ __forceinline__ void fma2(ull& c, ull a, ull b) {
    asm("fma.rn.f32x2 %0,%1,%2,%0;" : "+l"(c) : "l"(a), "l"(b));
}
__device__ __forceinline__ float2 unpack2(ull v) {
    float2 r; asm("mov.b64 {%0,%1},%2;" : "=f"(r.x), "=f"(r.y) : "l"(v)); return r;
}
__device__ __forceinline__ float ex2f_(float x) {
    float y; asm("ex2.approx.f32 %0,%1;" : "=f"(y) : "f"(x)); return y;
}
__device__ __forceinline__ float rcpf_(float x) {
    float y; asm("rcp.approx.f32 %0,%1;" : "=f"(y) : "f"(x)); return y;
}
__device__ __forceinline__ float sigm(float x) {
    return rcpf_(1.f + ex2f_(-1.4426950408889634f * x));
}
__device__ __forceinline__ float tanh_(float x) {
    return fmaf(-2.f, rcpf_(1.f + ex2f_(2.8853900817779268f * x)), 1.f);
}

// ---------------- init ----------------
__global__ void zero_state() {
    int idx = blockIdx.x * 256 + threadIdx.x;
    if (idx < T_*B_*H_) g_hrev[idx] = 0.f;
    if (idx < B_*H_)    g_hf[idx]   = 0.f;
    if (idx == 0)       g_bar       = 0u;
}

// ---------------- GEMM v2: C[M,N] = A[M,K] @ B[N,K]^T + bias ----------------
// 256 thr, tile 32x64. lane = row; warp w owns cols [w*8, w*8+8).
template<bool SIG>
__global__ __launch_bounds__(256) void gemm_v2(
    const float* __restrict__ A, const float* __restrict__ Bm,
    const float* __restrict__ bias, float* __restrict__ C,
    int M, int N, int K)
{
    __shared__ float As[32*33];
    __shared__ float Bs[32*68];
    const int tid  = threadIdx.x;
    const int lane = tid & 31;
    const int w    = tid >> 5;
    const int m0 = blockIdx.y * 32;
    const int n0 = blockIdx.x * 64;

    const int arow = tid >> 3, ak = (tid & 7) * 4;
    const int bcol = tid >> 2, bk = (tid & 3) * 4;
    const bool bvalid = (n0 + bcol) < N;
    const float* Aptr = A + (size_t)(m0 + arow) * K + ak;
    const float* Bptr = Bm + (size_t)(n0 + bcol) * K + bk;

    float4 pa = *(const float4*)Aptr;
    float4 pb0 = bvalid ? *(const float4*)(Bptr)      : make_float4(0,0,0,0);
    float4 pb1 = bvalid ? *(const float4*)(Bptr + 16) : make_float4(0,0,0,0);

    ull acc[4] = {0ull, 0ull, 0ull, 0ull};

    for (int k0 = 0; k0 < K; k0 += 32) {
        __syncthreads();
        As[(ak+0)*33 + arow] = pa.x;
        As[(ak+1)*33 + arow] = pa.y;
        As[(ak+2)*33 + arow] = pa.z;
        As[(ak+3)*33 + arow] = pa.w;
        Bs[(bk+0)*68 + bcol] = pb0.x;
        Bs[(bk+1)*68 + bcol] = pb0.y;
        Bs[(bk+2)*68 + bcol] = pb0.z;
        Bs[(bk+3)*68 + bcol] = pb0.w;
        Bs[(bk+16)*68 + bcol] = pb1.x;
        Bs[(bk+17)*68 + bcol] = pb1.y;
        Bs[(bk+18)*68 + bcol] = pb1.z;
        Bs[(bk+19)*68 + bcol] = pb1.w;
        __syncthreads();

        if (k0 + 32 < K) {
            pa = *(const float4*)(Aptr + k0 + 32);
            if (bvalid) {
                pb0 = *(const float4*)(Bptr + k0 + 32);
                pb1 = *(const float4*)(Bptr + k0 + 48);
            }
        }
#pragma unroll 8
        for (int kk = 0; kk < 32; kk++) {
            ull av = splat2(As[kk*33 + lane]);
            ulonglong2 L0 = *(const ulonglong2*)&Bs[kk*68 + (w<<3)];
            ulonglong2 L1 = *(const ulonglong2*)&Bs[kk*68 + (w<<3) + 4];
            fma2(acc[0], av, L0.x);
            fma2(acc[1], av, L0.y);
            fma2(acc[2], av, L1.x);
            fma2(acc[3], av, L1.y);
        }
    }

    const int row = m0 + lane;
#pragma unroll
    for (int p = 0; p < 4; p++) {
        int col = n0 + (w<<3) + 2*p;
        float2 v = unpack2(acc[p]);
        if (col + 1 < N) {
            v.x += bias[col]; v.y += bias[col+1];
            if (SIG) { v.x = sigm(v.x); v.y = sigm(v.y); }
            *(float2*)(C + (size_t)row * N + col) = v;
        } else if (col < N) {
            v.x += bias[col];
            if (SIG) v.x = sigm(v.x);
            C[(size_t)row * N + col] = v.x;
        }
    }
}

// ---------------- persistent recurrence kernel ----------------
// grid = 144 blocks (8 col-chunks x 18 slots), 256 threads, 229376B smem.
// Block (c, slot): owns h-cols [c*32, c*32+32); per step handles tasks
// y = slot, slot+18, ... <= 64-s  (y == 64-s is the fwd chain).
__global__ __launch_bounds__(256) void rnn_persist(
    const float* __restrict__ Whh_f, const float* __restrict__ Whh_r,
    const float* __restrict__ bhh_f, const float* __restrict__ bhh_r)
{
    extern __shared__ float sm[];
    float* WR = sm;               // [k][96] stride 96: 24576 floats
    float* WF = sm + 24576;
    float* HS = sm + 49152;       // [k][32] stride 32: 8192 floats

    const int tid  = threadIdx.x;
    const int lane = tid & 31;
    const int w    = tid >> 5;
    const int c0   = (blockIdx.x & 7) * 32;   // h-col base
    const int slot = blockIdx.x >> 3;

    // ---- stage both W slices (once per launch) ----
    {
        const float* srcs[2] = { Whh_r, Whh_f };
        float* dsts[2] = { WR, WF };
#pragma unroll
        for (int m = 0; m < 2; m++) {
            const float* Wg = srcs[m];
            float* Wb = dsts[m];
            for (int idx = tid; idx < 96*64; idx += 256) {
                int row = idx % 96;            // gate-col within slice
                int k4  = (idx / 96) * 4;
                int grow = (row >> 5) * 256 + c0 + (row & 31);
                float4 v = *(const float4*)(Wg + (size_t)grow * 256 + k4);
                Wb[(k4+0)*96 + row] = v.x;
                Wb[(k4+1)*96 + row] = v.y;
                Wb[(k4+2)*96 + row] = v.z;
                Wb[(k4+3)*96 + row] = v.w;
            }
        }
    }
    __syncthreads();

    const int hc = (w << 2);        // 4 h-cols per thread within chunk
    const int hcg = c0 + hc;

    unsigned int tgt = 0;
    for (int s = 0; s < 64; s++) {
        const int last = 64 - s;
        for (int y = slot; y <= last; y += SLOTS) {
            const bool isf = (y == last);
            const int i = s + y;
            float* hptr = isf ? g_hf : (g_hrev + (size_t)i * (B_*H_));
            const float* gib = isf ? (g_gif + (size_t)s * (B_*G_))
                                   : (g_gir + (size_t)(i - s) * (B_*G_));
            float* outp = isf ? (g_fwd + (size_t)s * (B_*H_))
                              : (g_rev + ((size_t)i * 64 + s) * (B_*H_));
            const float* Wb   = isf ? WF : WR;
            const float* bias = isf ? bhh_f : bhh_r;

            // stage h (32x256) transposed into HS[k][row]
            __syncthreads();
            {
                int row = tid >> 3, kb = (tid & 7) * 4;
                const float* src = hptr + row * 256 + kb;
#pragma unroll
                for (int q = 0; q < 8; q++) {
                    float4 v = *(const float4*)(src + q * 32);
                    int k = kb + q * 32;
                    HS[(k+0)*32 + row] = v.x;
                    HS[(k+1)*32 + row] = v.y;
                    HS[(k+2)*32 + row] = v.z;
                    HS[(k+3)*32 + row] = v.w;
                }
            }
            __syncthreads();

            // gemm: gh[lane][12 cols] = h[lane][:] @ W-slice
            ull a0=0,a1=0,a2=0,a3=0,a4=0,a5=0;
            const float* wk = Wb + hc;
#pragma unroll 8
            for (int k = 0; k < 256; k++) {
                ull av = splat2(HS[k*32 + lane]);
                ulonglong2 br_ = *(const ulonglong2*)(wk + k*96);
                ulonglong2 bz_ = *(const ulonglong2*)(wk + k*96 + 32);
                ulonglong2 bn_ = *(const ulonglong2*)(wk + k*96 + 64);
                fma2(a0, av, br_.x); fma2(a1, av, br_.y);
                fma2(a2, av, bz_.x); fma2(a3, av, bz_.y);
                fma2(a4, av, bn_.x); fma2(a5, av, bn_.y);
            }

            // pointwise GRU
            float2 r01 = unpack2(a0), r23 = unpack2(a1);
            float2 z01 = unpack2(a2), z23 = unpack2(a3);
            float2 n01 = unpack2(a4), n23 = unpack2(a5);
            float4 br = *(const float4*)(bias + hcg);
            float4 bz = *(const float4*)(bias + 256 + hcg);
            float4 bn = *(const float4*)(bias + 512 + hcg);
            const float* gi = gib + (size_t)lane * G_ + hcg;
            float4 gr = *(const float4*)gi;
            float4 gz = *(const float4*)(gi + 256);
            float4 gn = *(const float4*)(gi + 512);
            float* hrow = hptr + lane * 256 + hcg;
            float4 hp = *(const float4*)hrow;

            float r0 = sigm(gr.x + r01.x + br.x);
            float r1 = sigm(gr.y + r01.y + br.y);
            float r2 = sigm(gr.z + r23.x + br.z);
            float r3 = sigm(gr.w + r23.y + br.w);
            float z0 = sigm(gz.x + z01.x + bz.x);
            float z1 = sigm(gz.y + z01.y + bz.y);
            float z2 = sigm(gz.z + z23.x + bz.z);
            float z3 = sigm(gz.w + z23.y + bz.w);
            float n0 = tanh_(gn.x + r0 * (n01.x + bn.x));
            float n1 = tanh_(gn.y + r1 * (n01.y + bn.y));
            float n2 = tanh_(gn.z + r2 * (n23.x + bn.z));
            float n3 = tanh_(gn.w + r3 * (n23.y + bn.w));
            float4 hv;
            hv.x = (1.f - z0) * n0 + z0 * hp.x;
            hv.y = (1.f - z1) * n1 + z1 * hp.y;
            hv.z = (1.f - z2) * n2 + z2 * hp.z;
            hv.w = (1.f - z3) * n3 + z3 * hp.w;
            *(float4*)hrow = hv;
            *(float4*)(outp + lane * 256 + hcg) = hv;
        }

        // ---- grid barrier (release/acquire via L2) ----
        if (s != 63) {
            __syncthreads();
            tgt += NBLK;
            if (tid == 0) {
                __threadfence();                 // release h writes
                atomicAdd(&g_bar, 1u);
                volatile unsigned int* p = &g_bar;
                while (*p < tgt) { }
                __threadfence();                 // acquire
            }
            __syncthreads();
        }
    }
}

// ---------------- attention ----------------
__global__ __launch_bounds__(256) void scores_k(
    const float* __restrict__ attn_w, const float* __restrict__ attn_b)
{
    const int i = blockIdx.x;
    const int w = threadIdx.x >> 5, l = threadIdx.x & 31;
    __shared__ float wf[256], wr[256];
    wf[threadIdx.x] = attn_w[threadIdx.x];
    wr[threadIdx.x] = attn_w[256 + threadIdx.x];
    __syncthreads();
    float ab = attn_b[0];
    for (int t = 0; t <= i; t++) {
#pragma unroll
        for (int bb = 0; bb < 4; bb++) {
            int b = w * 4 + bb;
            const float* fp = g_fwd + ((size_t)(t*32 + b)) * 256 + l*8;
            const float* rp = g_rev + ((size_t)((i*64 + t)*32 + b)) * 256 + l*8;
            float acc = 0.f;
#pragma unroll
            for (int q = 0; q < 8; q++)
                acc += fp[q]*wf[l*8+q] + rp[q]*wr[l*8+q];
#pragma unroll
            for (int o = 16; o; o >>= 1) acc += __shfl_xor_sync(0xffffffffu, acc, o);
            if (l == 0) g_sc[(i*64 + t)*32 + b] = acc + ab;
        }
    }
}

__global__ void softmax_k() {
    const int i = blockIdx.x;
    const int b = threadIdx.x;
    float m = -1e30f;
    for (int t = 0; t <= i; t++) m = fmaxf(m, g_sc[(i*64 + t)*32 + b]);
    float ssum = 0.f;
    for (int t = 0; t <= i; t++) {
        float e = ex2f_(1.4426950408889634f * (g_sc[(i*64 + t)*32 + b] - m));
        g_sc[(i*64 + t)*32 + b] = e;
        ssum += e;
    }
    float inv = 1.f / ssum;
    for (int t = 0; t <= i; t++) g_sc[(i*64 + t)*32 + b] *= inv;
}

__global__ __launch_bounds__(256) void context_k() {
    const int i = blockIdx.x, bg = blockIdx.y;
    const int h = threadIdx.x;
    float accf[8], accr[8];
#pragma unroll
    for (int j = 0; j < 8; j++) { accf[j] = 0.f; accr[j] = 0.f; }
    for (int t = 0; t <= i; t++) {
        const float* al = g_sc + (i*64 + t)*32 + bg*8;
        const float* fr = g_fwd + ((size_t)(t*32 + bg*8)) * 256 + h;
        const float* rr = g_rev + ((size_t)((i*64 + t)*32 + bg*8)) * 256 + h;
#pragma unroll
        for (int j = 0; j < 8; j++) {
            float a = al[j];
            accf[j] += a * fr[(size_t)j*256];
            accr[j] += a * rr[(size_t)j*256];
        }
    }
    float inv = 1.f / (float)(i + 1);
#pragma unroll
    for (int j = 0; j < 8; j++) {
        int b = bg*8 + j;
        size_t row = (size_t)(i*32 + b);
        g_ht[row*1024 + h]       = accf[j] * inv;
        g_ht[row*1024 + 256 + h] = accr[j] * inv;
        g_ht[row*1024 + 512 + h] = g_fwd[((size_t)(i*32 + b))*256 + h];
        g_ht[row*1024 + 768 + h] = g_rev[((size_t)((i*64 + i)*32 + b))*256 + h];
    }
}

// ---------------- launch ----------------
extern "C" void kernel_launch(void* const* d_in, const int* in_sizes, int n_in,
                              void* d_out, int out_size)
{
    const float* x      = (const float*)d_in[0];
    const float* W_emb  = (const float*)d_in[1];
    const float* b_emb  = (const float*)d_in[2];
    const float* Wih_f  = (const float*)d_in[3];
    const float* Whh_f  = (const float*)d_in[4];
    const float* bih_f  = (const float*)d_in[5];
    const float* bhh_f  = (const float*)d_in[6];
    const float* Wih_r  = (const float*)d_in[7];
    const float* Whh_r  = (const float*)d_in[8];
    const float* bih_r  = (const float*)d_in[9];
    const float* bhh_r  = (const float*)d_in[10];
    const float* attn_w = (const float*)d_in[11];
    const float* attn_b = (const float*)d_in[12];
    const float* W_ao   = (const float*)d_in[13];
    const float* b_ao   = (const float*)d_in[14];
    const float* W_o    = (const float*)d_in[15];
    const float* b_o    = (const float*)d_in[16];
    float* out = (float*)d_out;

    void *p_day, *p_gif, *p_gir, *p_ht, *p_hto;
    cudaGetSymbolAddress(&p_day, g_day);
    cudaGetSymbolAddress(&p_gif, g_gif);
    cudaGetSymbolAddress(&p_gir, g_gir);
    cudaGetSymbolAddress(&p_ht,  g_ht);
    cudaGetSymbolAddress(&p_hto, g_hto);

    const int RNN_SMEM = (24576*2 + 8192) * 4;   // 229376 bytes
    static int attr_set = 0;
    cudaFuncSetAttribute(rnn_persist, cudaFuncAttributeMaxDynamicSharedMemorySize, RNN_SMEM);
    (void)attr_set;

    zero_state<<<2048, 256>>>();

    gemm_v2<false><<<dim3(4, 64), 256>>>(x, W_emb, b_emb, (float*)p_day, M_, DD_, DIN_);
    gemm_v2<false><<<dim3(12, 64), 256>>>((const float*)p_day, Wih_f, bih_f, (float*)p_gif, M_, G_, DD_);
    gemm_v2<false><<<dim3(12, 64), 256>>>((const float*)p_day, Wih_r, bih_r, (float*)p_gir, M_, G_, DD_);

    rnn_persist<<<NBLK, 256, RNN_SMEM>>>(Whh_f, Whh_r, bhh_f, bhh_r);

    scores_k<<<64, 256>>>(attn_w, attn_b);
    softmax_k<<<64, 32>>>();
    context_k<<<dim3(64, 4), 256>>>();

    gemm_v2<false><<<dim3(4, 64), 256>>>((const float*)p_ht, W_ao, b_ao, (float*)p_hto, M_, DD_, 4*H_);
    gemm_v2<true><<<dim3(15, 64), 256>>>((const float*)p_hto, W_o, b_o, out, M_, DOUT_, DD_);
}

// round 4
// speedup vs baseline: 1.0813x; 1.0677x over previous
#include <cuda_runtime.h>
#include <math.h>

typedef unsigned long long ull;

#define T_   64
#define B_   32
#define H_   256
#define G_   768
#define DD_  256
#define DIN_ 4096
#define DOUT_ 942
#define M_   (T_*B_)

#define NCHAIN 65          // 64 rev chains + 1 fwd chain
#define CLSZ   8           // CTAs per cluster (one per 32-col h chunk)
#define HS_STRIDE 257      // conflict-free row-major h stage

// ---------------- device scratch (static; no allocations) ----------------
__device__ float g_day [M_*DD_];
__device__ float g_gif [M_*G_];
__device__ float g_gir [M_*G_];
__device__ float g_hA  [NCHAIN*B_*H_];    // h state ping
__device__ float g_hB  [NCHAIN*B_*H_];    // h state pong
__device__ float g_fwd [T_*B_*H_];
__device__ float g_rev [T_*T_*B_*H_];     // [i][t][b][h], t<=i valid
__device__ float g_sc  [T_*T_*B_];
__device__ float g_ht  [M_*4*H_];
__device__ float g_hto [M_*DD_];

// ---------------- math helpers ----------------
__device__ __forceinline__ ull splat2(float x) {
    ull r; asm("mov.b64 %0,{%1,%1};" : "=l"(r) : "f"(x)); return r;
}
__device__ __forceinline__ void fma2(ull& c, ull a, ull b) {
    asm("fma.rn.f32x2 %0,%1,%2,%0;" : "+l"(c) : "l"(a), "l"(b));
}
__device__ __forceinline__ float2 unpack2(ull v) {
    float2 r; asm("mov.b64 {%0,%1},%2;" : "=f"(r.x), "=f"(r.y) : "l"(v)); return r;
}
__device__ __forceinline__ float ex2f_(float x) {
    float y; asm("ex2.approx.f32 %0,%1;" : "=f"(y) : "f"(x)); return y;
}
__device__ __forceinline__ float rcpf_(float x) {
    float y; asm("rcp.approx.f32 %0,%1;" : "=f"(y) : "f"(x)); return y;
}
__device__ __forceinline__ float sigm(float x) {
    return rcpf_(1.f + ex2f_(-1.4426950408889634f * x));
}
__device__ __forceinline__ float tanh_(float x) {
    return fmaf(-2.f, rcpf_(1.f + ex2f_(2.8853900817779268f * x)), 1.f);
}

// ---------------- init ----------------
__global__ void zero_state() {
    int idx = blockIdx.x * 256 + threadIdx.x;
    if (idx < NCHAIN*B_*H_) g_hA[idx] = 0.f;
}

// ---------------- GEMM: C[M,N] = A[M,K] @ B[N,K]^T + bias ----------------
template<bool SIG>
__global__ __launch_bounds__(256) void gemm_v2(
    const float* __restrict__ A, const float* __restrict__ Bm,
    const float* __restrict__ bias, float* __restrict__ C,
    int M, int N, int K)
{
    __shared__ float As[32*33];
    __shared__ float Bs[32*68];
    const int tid  = threadIdx.x;
    const int lane = tid & 31;
    const int w    = tid >> 5;
    const int m0 = blockIdx.y * 32;
    const int n0 = blockIdx.x * 64;

    const int arow = tid >> 3, ak = (tid & 7) * 4;
    const int bcol = tid >> 2, bk = (tid & 3) * 4;
    const bool bvalid = (n0 + bcol) < N;
    const float* Aptr = A + (size_t)(m0 + arow) * K + ak;
    const float* Bptr = Bm + (size_t)(n0 + bcol) * K + bk;

    float4 pa = *(const float4*)Aptr;
    float4 pb0 = bvalid ? *(const float4*)(Bptr)      : make_float4(0,0,0,0);
    float4 pb1 = bvalid ? *(const float4*)(Bptr + 16) : make_float4(0,0,0,0);

    ull acc[4] = {0ull, 0ull, 0ull, 0ull};

    for (int k0 = 0; k0 < K; k0 += 32) {
        __syncthreads();
        As[(ak+0)*33 + arow] = pa.x;
        As[(ak+1)*33 + arow] = pa.y;
        As[(ak+2)*33 + arow] = pa.z;
        As[(ak+3)*33 + arow] = pa.w;
        Bs[(bk+0)*68 + bcol] = pb0.x;
        Bs[(bk+1)*68 + bcol] = pb0.y;
        Bs[(bk+2)*68 + bcol] = pb0.z;
        Bs[(bk+3)*68 + bcol] = pb0.w;
        Bs[(bk+16)*68 + bcol] = pb1.x;
        Bs[(bk+17)*68 + bcol] = pb1.y;
        Bs[(bk+18)*68 + bcol] = pb1.z;
        Bs[(bk+19)*68 + bcol] = pb1.w;
        __syncthreads();

        if (k0 + 32 < K) {
            pa = *(const float4*)(Aptr + k0 + 32);
            if (bvalid) {
                pb0 = *(const float4*)(Bptr + k0 + 32);
                pb1 = *(const float4*)(Bptr + k0 + 48);
            }
        }
#pragma unroll 8
        for (int kk = 0; kk < 32; kk++) {
            ull av = splat2(As[kk*33 + lane]);
            ulonglong2 L0 = *(const ulonglong2*)&Bs[kk*68 + (w<<3)];
            ulonglong2 L1 = *(const ulonglong2*)&Bs[kk*68 + (w<<3) + 4];
            fma2(acc[0], av, L0.x);
            fma2(acc[1], av, L0.y);
            fma2(acc[2], av, L1.x);
            fma2(acc[3], av, L1.y);
        }
    }

    const int row = m0 + lane;
#pragma unroll
    for (int p = 0; p < 4; p++) {
        int col = n0 + (w<<3) + 2*p;
        float2 v = unpack2(acc[p]);
        if (col + 1 < N) {
            v.x += bias[col]; v.y += bias[col+1];
            if (SIG) { v.x = sigm(v.x); v.y = sigm(v.y); }
            *(float2*)(C + (size_t)row * N + col) = v;
        } else if (col < N) {
            v.x += bias[col];
            if (SIG) v.x = sigm(v.x);
            C[(size_t)row * N + col] = v.x;
        }
    }
}

// ---------------- per-chain cluster recurrence ----------------
// 520 blocks = 65 clusters of 8. Cluster c: c==0 -> fwd chain (len 64),
// c>=1 -> rev chain i=64-c (len i+1). Block = one 32-col h chunk.
// smem: W slice [k][96] (98304B) + HS [b][k] stride 257 (32896B) = 131200B.
__global__ __launch_bounds__(256) __cluster_dims__(CLSZ, 1, 1)
void chain_rnn(const float* __restrict__ Whh_f, const float* __restrict__ Whh_r,
               const float* __restrict__ bhh_f, const float* __restrict__ bhh_r)
{
    extern __shared__ float sm[];
    float* WS = sm;             // 24576 floats
    float* HS = sm + 24576;     // 32*257 floats

    const int tid  = threadIdx.x;
    const int lane = tid & 31;
    const int w    = tid >> 5;
    const int cidx = blockIdx.x >> 3;
    const int c0   = (blockIdx.x & 7) * 32;

    const bool isf = (cidx == 0);
    const int i    = 64 - cidx;            // rev chain id (cidx>=1)
    const int len  = isf ? 64 : (i + 1);

    const float* Wg   = isf ? Whh_f : Whh_r;
    const float* bias = isf ? bhh_f : bhh_r;

    // ---- stage W slice once (rows: r[0..31], z[32..63], n[64..95]) ----
    for (int idx = tid; idx < 96*64; idx += 256) {
        int row = idx % 96;
        int k4  = (idx / 96) * 4;
        int grow = (row >> 5) * 256 + c0 + (row & 31);
        float4 v = *(const float4*)(Wg + (size_t)grow * 256 + k4);
        WS[(k4+0)*96 + row] = v.x;
        WS[(k4+1)*96 + row] = v.y;
        WS[(k4+2)*96 + row] = v.z;
        WS[(k4+3)*96 + row] = v.w;
    }

    const int hc  = w << 2;        // 4 h-cols per thread
    const int hcg = c0 + hc;
    const float4 br = *(const float4*)(bias + hcg);
    const float4 bz = *(const float4*)(bias + 256 + hcg);
    const float4 bn = *(const float4*)(bias + 512 + hcg);

    float* bufA = g_hA + (size_t)cidx * (B_*H_);
    float* bufB = g_hB + (size_t)cidx * (B_*H_);

    const int srow = tid >> 3;            // staging row 0..31
    const int skb  = (tid & 7) * 4;       // staging k base

    __syncthreads();   // WS ready

    for (int s = 0; s < len; s++) {
        float* hsrc = (s & 1) ? bufB : bufA;
        float* hdst = (s & 1) ? bufA : bufB;

        // ---- stage h (32x256) row-major, conflict-free ----
        {
            const float* src = hsrc + srow * 256 + skb;
            float* d = HS + srow * HS_STRIDE + skb;
#pragma unroll
            for (int q = 0; q < 8; q++) {
                float4 v = __ldcg((const float4*)(src + q * 32));
                d[q*32 + 0] = v.x;
                d[q*32 + 1] = v.y;
                d[q*32 + 2] = v.z;
                d[q*32 + 3] = v.w;
            }
        }
        __syncthreads();

        // ---- gh = h @ W-slice (per-lane batch row, broadcast W) ----
        ull a0=0,a1=0,a2=0,a3=0,a4=0,a5=0;
        const float* wk = WS + hc;
        const float* hk = HS + lane * HS_STRIDE;
#pragma unroll 8
        for (int k = 0; k < 256; k++) {
            ull av = splat2(hk[k]);
            ulonglong2 rr_ = *(const ulonglong2*)(wk + k*96);
            ulonglong2 zz_ = *(const ulonglong2*)(wk + k*96 + 32);
            ulonglong2 nn_ = *(const ulonglong2*)(wk + k*96 + 64);
            fma2(a0, av, rr_.x); fma2(a1, av, rr_.y);
            fma2(a2, av, zz_.x); fma2(a3, av, zz_.y);
            fma2(a4, av, nn_.x); fma2(a5, av, nn_.y);
        }

        // ---- fused GRU pointwise ----
        float2 r01 = unpack2(a0), r23 = unpack2(a1);
        float2 z01 = unpack2(a2), z23 = unpack2(a3);
        float2 n01 = unpack2(a4), n23 = unpack2(a5);

        const float* gi = (isf ? (g_gif + (size_t)s * (B_*G_))
                               : (g_gir + (size_t)(i - s) * (B_*G_)))
                          + (size_t)lane * G_ + hcg;
        float4 gr = *(const float4*)gi;
        float4 gz = *(const float4*)(gi + 256);
        float4 gn = *(const float4*)(gi + 512);

        const float* hkp = hk + hcg;    // h_prev from smem stage
        float hp0 = hkp[0], hp1 = hkp[1], hp2 = hkp[2], hp3 = hkp[3];

        float r0 = sigm(gr.x + r01.x + br.x);
        float r1 = sigm(gr.y + r01.y + br.y);
        float r2 = sigm(gr.z + r23.x + br.z);
        float r3 = sigm(gr.w + r23.y + br.w);
        float z0 = sigm(gz.x + z01.x + bz.x);
        float z1 = sigm(gz.y + z01.y + bz.y);
        float z2 = sigm(gz.z + z23.x + bz.z);
        float z3 = sigm(gz.w + z23.y + bz.w);
        float n0 = tanh_(gn.x + r0 * (n01.x + bn.x));
        float n1 = tanh_(gn.y + r1 * (n01.y + bn.y));
        float n2 = tanh_(gn.z + r2 * (n23.x + bn.z));
        float n3 = tanh_(gn.w + r3 * (n23.y + bn.w));
        float4 hv;
        hv.x = (1.f - z0) * n0 + z0 * hp0;
        hv.y = (1.f - z1) * n1 + z1 * hp1;
        hv.z = (1.f - z2) * n2 + z2 * hp2;
        hv.w = (1.f - z3) * n3 + z3 * hp3;

        __stcg((float4*)(hdst + lane * 256 + hcg), hv);
        float* outp = isf ? (g_fwd + (size_t)s * (B_*H_))
                          : (g_rev + ((size_t)i * 64 + s) * (B_*H_));
        *(float4*)(outp + lane * 256 + hcg) = hv;

        if (s != len - 1) {
            asm volatile("barrier.cluster.arrive.aligned;" ::: "memory");
            asm volatile("barrier.cluster.wait.aligned;"   ::: "memory");
        }
    }
}

// ---------------- attention ----------------
__global__ __launch_bounds__(256) void scores_k(
    const float* __restrict__ attn_w, const float* __restrict__ attn_b)
{
    const int i = blockIdx.x;
    const int w = threadIdx.x >> 5, l = threadIdx.x & 31;
    __shared__ float wf[256], wr[256];
    wf[threadIdx.x] = attn_w[threadIdx.x];
    wr[threadIdx.x] = attn_w[256 + threadIdx.x];
    __syncthreads();
    float ab = attn_b[0];
    for (int t = 0; t <= i; t++) {
#pragma unroll
        for (int bb = 0; bb < 4; bb++) {
            int b = w * 4 + bb;
            const float* fp = g_fwd + ((size_t)(t*32 + b)) * 256 + l*8;
            const float* rp = g_rev + ((size_t)((i*64 + t)*32 + b)) * 256 + l*8;
            float acc = 0.f;
#pragma unroll
            for (int q = 0; q < 8; q++)
                acc += fp[q]*wf[l*8+q] + rp[q]*wr[l*8+q];
#pragma unroll
            for (int o = 16; o; o >>= 1) acc += __shfl_xor_sync(0xffffffffu, acc, o);
            if (l == 0) g_sc[(i*64 + t)*32 + b] = acc + ab;
        }
    }
}

__global__ void softmax_k() {
    const int i = blockIdx.x;
    const int b = threadIdx.x;
    float m = -1e30f;
    for (int t = 0; t <= i; t++) m = fmaxf(m, g_sc[(i*64 + t)*32 + b]);
    float ssum = 0.f;
    for (int t = 0; t <= i; t++) {
        float e = ex2f_(1.4426950408889634f * (g_sc[(i*64 + t)*32 + b] - m));
        g_sc[(i*64 + t)*32 + b] = e;
        ssum += e;
    }
    float inv = 1.f / ssum;
    for (int t = 0; t <= i; t++) g_sc[(i*64 + t)*32 + b] *= inv;
}

__global__ __launch_bounds__(256) void context_k() {
    const int i = blockIdx.x, bg = blockIdx.y;
    const int h = threadIdx.x;
    float accf[8], accr[8];
#pragma unroll
    for (int j = 0; j < 8; j++) { accf[j] = 0.f; accr[j] = 0.f; }
    for (int t = 0; t <= i; t++) {
        const float* al = g_sc + (i*64 + t)*32 + bg*8;
        const float* fr = g_fwd + ((size_t)(t*32 + bg*8)) * 256 + h;
        const float* rr = g_rev + ((size_t)((i*64 + t)*32 + bg*8)) * 256 + h;
#pragma unroll
        for (int j = 0; j < 8; j++) {
            float a = al[j];
            accf[j] += a * fr[(size_t)j*256];
            accr[j] += a * rr[(size_t)j*256];
        }
    }
    float inv = 1.f / (float)(i + 1);
#pragma unroll
    for (int j = 0; j < 8; j++) {
        int b = bg*8 + j;
        size_t row = (size_t)(i*32 + b);
        g_ht[row*1024 + h]       = accf[j] * inv;
        g_ht[row*1024 + 256 + h] = accr[j] * inv;
        g_ht[row*1024 + 512 + h] = g_fwd[((size_t)(i*32 + b))*256 + h];
        g_ht[row*1024 + 768 + h] = g_rev[((size_t)((i*64 + i)*32 + b))*256 + h];
    }
}

// ---------------- launch ----------------
extern "C" void kernel_launch(void* const* d_in, const int* in_sizes, int n_in,
                              void* d_out, int out_size)
{
    const float* x      = (const float*)d_in[0];
    const float* W_emb  = (const float*)d_in[1];
    const float* b_emb  = (const float*)d_in[2];
    const float* Wih_f  = (const float*)d_in[3];
    const float* Whh_f  = (const float*)d_in[4];
    const float* bih_f  = (const float*)d_in[5];
    const float* bhh_f  = (const float*)d_in[6];
    const float* Wih_r  = (const float*)d_in[7];
    const float* Whh_r  = (const float*)d_in[8];
    const float* bih_r  = (const float*)d_in[9];
    const float* bhh_r  = (const float*)d_in[10];
    const float* attn_w = (const float*)d_in[11];
    const float* attn_b = (const float*)d_in[12];
    const float* W_ao   = (const float*)d_in[13];
    const float* b_ao   = (const float*)d_in[14];
    const float* W_o    = (const float*)d_in[15];
    const float* b_o    = (const float*)d_in[16];
    float* out = (float*)d_out;

    void *p_day, *p_gif, *p_gir, *p_ht, *p_hto;
    cudaGetSymbolAddress(&p_day, g_day);
    cudaGetSymbolAddress(&p_gif, g_gif);
    cudaGetSymbolAddress(&p_gir, g_gir);
    cudaGetSymbolAddress(&p_ht,  g_ht);
    cudaGetSymbolAddress(&p_hto, g_hto);

    const int RNN_SMEM = (24576 + 32*HS_STRIDE) * 4;   // 131200 B
    cudaFuncSetAttribute(chain_rnn, cudaFuncAttributeMaxDynamicSharedMemorySize, RNN_SMEM);

    zero_state<<<(NCHAIN*B_*H_ + 255) / 256, 256>>>();

    gemm_v2<false><<<dim3(4, 64), 256>>>(x, W_emb, b_emb, (float*)p_day, M_, DD_, DIN_);
    gemm_v2<false><<<dim3(12, 64), 256>>>((const float*)p_day, Wih_f, bih_f, (float*)p_gif, M_, G_, DD_);
    gemm_v2<false><<<dim3(12, 64), 256>>>((const float*)p_day, Wih_r, bih_r, (float*)p_gir, M_, G_, DD_);

    chain_rnn<<<NCHAIN*CLSZ, 256, RNN_SMEM>>>(Whh_f, Whh_r, bhh_f, bhh_r);

    scores_k<<<64, 256>>>(attn_w, attn_b);
    softmax_k<<<64, 32>>>();
    context_k<<<dim3(64, 4), 256>>>();

    gemm_v2<false><<<dim3(4, 64), 256>>>((const float*)p_ht, W_ao, b_ao, (float*)p_hto, M_, DD_, 4*H_);
    gemm_v2<true><<<dim3(15, 64), 256>>>((const float*)p_hto, W_o, b_o, out, M_, DOUT_, DD_);
}

// round 5
// speedup vs baseline: 1.1457x; 1.0596x over previous
#include <cuda_runtime.h>
#include <math.h>

typedef unsigned long long ull;

#define T_   64
#define B_   32
#define H_   256
#define G_   768
#define DD_  256
#define DIN_ 4096
#define DOUT_ 942
#define M_   (T_*B_)

#define NCHAIN 65
#define CLSZ   8
#define HS_STRIDE 260      // %32 == 4 -> conflict-free float4 LDS/STS

// ---------------- device scratch (static; no allocations) ----------------
__device__ float g_day [M_*DD_];
__device__ float g_gif [M_*G_];
__device__ float g_gir [M_*G_];
__device__ float g_hA  [NCHAIN*B_*H_];
__device__ float g_hB  [NCHAIN*B_*H_];
__device__ float g_fwd [T_*B_*H_];
__device__ float g_rev [T_*T_*B_*H_];       // [i][t][b][h], t<=i valid
__device__ float g_scrp[8*T_*T_*B_];        // rev score partials [chunk][i][t][b]
__device__ float g_scfp[8*T_*B_];           // fwd score partials [chunk][t][b]
__device__ float g_sc  [T_*T_*B_];          // alpha [i][t][b]
__device__ float g_ht  [M_*4*H_];
__device__ float g_hto [M_*DD_];

#define ZHA  (NCHAIN*B_*H_)                 // 532480
#define ZRP  (8*T_*T_*B_)                   // 1048576
#define ZFP  (8*T_*B_)                      // 16384
#define ZTOT (ZHA+ZRP+ZFP)

// ---------------- math helpers ----------------
__device__ __forceinline__ ull splat2(float x) {
    ull r; asm("mov.b64 %0,{%1,%1};" : "=l"(r) : "f"(x)); return r;
}
__device__ __forceinline__ void fma2(ull& c, ull a, ull b) {
    asm("fma.rn.f32x2 %0,%1,%2,%0;" : "+l"(c) : "l"(a), "l"(b));
}
__device__ __forceinline__ float2 unpack2(ull v) {
    float2 r; asm("mov.b64 {%0,%1},%2;" : "=f"(r.x), "=f"(r.y) : "l"(v)); return r;
}
__device__ __forceinline__ float ex2f_(float x) {
    float y; asm("ex2.approx.f32 %0,%1;" : "=f"(y) : "f"(x)); return y;
}
__device__ __forceinline__ float rcpf_(float x) {
    float y; asm("rcp.approx.f32 %0,%1;" : "=f"(y) : "f"(x)); return y;
}
__device__ __forceinline__ float sigm(float x) {
    return rcpf_(1.f + ex2f_(-1.4426950408889634f * x));
}
__device__ __forceinline__ float tanh_(float x) {
    return fmaf(-2.f, rcpf_(1.f + ex2f_(2.8853900817779268f * x)), 1.f);
}

// ---------------- GEMM core: C[M,N] = A[M,K] @ B[N,K]^T + bias ----------------
template<bool SIG>
__device__ __forceinline__ void gemm_body(
    const float* __restrict__ A, const float* __restrict__ Bm,
    const float* __restrict__ bias, float* __restrict__ C,
    int M, int N, int K, int m0, int n0,
    float* As, float* Bs)
{
    const int tid  = threadIdx.x;
    const int lane = tid & 31;
    const int w    = tid >> 5;

    const int arow = tid >> 3, ak = (tid & 7) * 4;
    const int bcol = tid >> 2, bk = (tid & 3) * 4;
    const bool bvalid = (n0 + bcol) < N;
    const float* Aptr = A + (size_t)(m0 + arow) * K + ak;
    const float* Bptr = Bm + (size_t)(n0 + bcol) * K + bk;

    float4 pa = *(const float4*)Aptr;
    float4 pb0 = bvalid ? *(const float4*)(Bptr)      : make_float4(0,0,0,0);
    float4 pb1 = bvalid ? *(const float4*)(Bptr + 16) : make_float4(0,0,0,0);

    ull acc[4] = {0ull, 0ull, 0ull, 0ull};

    for (int k0 = 0; k0 < K; k0 += 32) {
        __syncthreads();
        As[(ak+0)*33 + arow] = pa.x;
        As[(ak+1)*33 + arow] = pa.y;
        As[(ak+2)*33 + arow] = pa.z;
        As[(ak+3)*33 + arow] = pa.w;
        Bs[(bk+0)*68 + bcol] = pb0.x;
        Bs[(bk+1)*68 + bcol] = pb0.y;
        Bs[(bk+2)*68 + bcol] = pb0.z;
        Bs[(bk+3)*68 + bcol] = pb0.w;
        Bs[(bk+16)*68 + bcol] = pb1.x;
        Bs[(bk+17)*68 + bcol] = pb1.y;
        Bs[(bk+18)*68 + bcol] = pb1.z;
        Bs[(bk+19)*68 + bcol] = pb1.w;
        __syncthreads();

        if (k0 + 32 < K) {
            pa = *(const float4*)(Aptr + k0 + 32);
            if (bvalid) {
                pb0 = *(const float4*)(Bptr + k0 + 32);
                pb1 = *(const float4*)(Bptr + k0 + 48);
            }
        }
#pragma unroll 8
        for (int kk = 0; kk < 32; kk++) {
            ull av = splat2(As[kk*33 + lane]);
            ulonglong2 L0 = *(const ulonglong2*)&Bs[kk*68 + (w<<3)];
            ulonglong2 L1 = *(const ulonglong2*)&Bs[kk*68 + (w<<3) + 4];
            fma2(acc[0], av, L0.x);
            fma2(acc[1], av, L0.y);
            fma2(acc[2], av, L1.x);
            fma2(acc[3], av, L1.y);
        }
    }

    const int row = m0 + lane;
#pragma unroll
    for (int p = 0; p < 4; p++) {
        int col = n0 + (w<<3) + 2*p;
        float2 v = unpack2(acc[p]);
        if (col + 1 < N) {
            v.x += bias[col]; v.y += bias[col+1];
            if (SIG) { v.x = sigm(v.x); v.y = sigm(v.y); }
            *(float2*)(C + (size_t)row * N + col) = v;
        } else if (col < N) {
            v.x += bias[col];
            if (SIG) v.x = sigm(v.x);
            C[(size_t)row * N + col] = v.x;
        }
    }
}

template<bool SIG>
__global__ __launch_bounds__(256) void gemm_v2(
    const float* __restrict__ A, const float* __restrict__ Bm,
    const float* __restrict__ bias, float* __restrict__ C,
    int M, int N, int K)
{
    __shared__ float As[32*33];
    __shared__ float Bs[32*68];
    gemm_body<SIG>(A, Bm, bias, C, M, N, K, blockIdx.y*32, blockIdx.x*64, As, Bs);
}

// gi fused GEMM (z=0: fwd weights, z=1: rev) + zero-state prologue
__global__ __launch_bounds__(256) void gi_fused(
    const float* __restrict__ Wih_f, const float* __restrict__ bih_f,
    const float* __restrict__ Wih_r, const float* __restrict__ bih_r)
{
    __shared__ float As[32*33];
    __shared__ float Bs[32*68];

    // zero prologue: 1536 blocks cover ZTOT floats
    {
        int flat = blockIdx.x + 12*(blockIdx.y + 64*blockIdx.z);
        const int per = (ZTOT + 1535) / 1536;     // 1040
        int base = flat * per;
        int end  = base + per; if (end > ZTOT) end = ZTOT;
        for (int j = base + threadIdx.x; j < end; j += 256) {
            if (j < ZHA)            g_hA[j] = 0.f;
            else if (j < ZHA+ZRP)   g_scrp[j - ZHA] = 0.f;
            else                    g_scfp[j - ZHA - ZRP] = 0.f;
        }
    }

    const bool r = (blockIdx.z == 1);
    gemm_body<false>(g_day, r ? Wih_r : Wih_f, r ? bih_r : bih_f,
                     r ? g_gir : g_gif, M_, G_, DD_,
                     blockIdx.y*32, blockIdx.x*64, As, Bs);
}

// ---------------- per-chain cluster recurrence (+ in-chain attention dots) --
// 520 blocks = 65 clusters of 8. cidx 0 -> fwd chain (len 64); cidx>=1 ->
// rev chain i = 64-cidx (len i+1). Block = one 32-col h chunk.
__global__ __launch_bounds__(256) __cluster_dims__(CLSZ, 1, 1)
void chain_rnn(const float* __restrict__ Whh_f, const float* __restrict__ Whh_r,
               const float* __restrict__ bhh_f, const float* __restrict__ bhh_r,
               const float* __restrict__ attn_w)
{
    extern __shared__ float sm[];
    float* WS = sm;                       // 96 x 256: 24576 floats
    float* HS = sm + 24576;               // 32 x HS_STRIDE
    float* SB = sm + 24576 + 32*HS_STRIDE; // 8 x 32 score partials

    const int tid   = threadIdx.x;
    const int lane  = tid & 31;
    const int w     = tid >> 5;
    const int cidx  = blockIdx.x >> 3;
    const int chunk = blockIdx.x & 7;
    const int c0    = chunk * 32;

    const bool isf = (cidx == 0);
    const int i    = 64 - cidx;
    const int len  = isf ? 64 : (i + 1);

    const float* Wg   = isf ? Whh_f : Whh_r;
    const float* bias = isf ? bhh_f : bhh_r;

    // stage W slice once (gate rows r[0..31], z[32..63], n[64..95])
    for (int idx = tid; idx < 96*64; idx += 256) {
        int row = idx % 96;
        int k4  = (idx / 96) * 4;
        int grow = (row >> 5) * 256 + c0 + (row & 31);
        float4 v = *(const float4*)(Wg + (size_t)grow * 256 + k4);
        WS[(k4+0)*96 + row] = v.x;
        WS[(k4+1)*96 + row] = v.y;
        WS[(k4+2)*96 + row] = v.z;
        WS[(k4+3)*96 + row] = v.w;
    }

    const int hc  = w << 2;
    const int hcg = c0 + hc;
    const float4 br = *(const float4*)(bias + hcg);
    const float4 bz = *(const float4*)(bias + 256 + hcg);
    const float4 bn = *(const float4*)(bias + 512 + hcg);
    const float4 wv = *(const float4*)(attn_w + (isf ? 0 : 256) + hcg);

    float* bufA = g_hA + (size_t)cidx * (B_*H_);
    float* bufB = g_hB + (size_t)cidx * (B_*H_);

    const int srow = tid >> 3;
    const int skb  = (tid & 7) * 4;

    __syncthreads();

    for (int s = 0; s < len; s++) {
        float* hsrc = (s & 1) ? bufB : bufA;
        float* hdst = (s & 1) ? bufA : bufB;

        // stage h (32x256) via float4, conflict-free
        {
            const float* src = hsrc + srow * 256 + skb;
            float* d = HS + srow * HS_STRIDE + skb;
#pragma unroll
            for (int q = 0; q < 8; q++)
                *(float4*)(d + q*32) = __ldcg((const float4*)(src + q * 32));
        }
        __syncthreads();

        // gi loads early (hidden under gemm)
        const float* gi = (isf ? (g_gif + (size_t)s * (B_*G_))
                               : (g_gir + (size_t)(i - s) * (B_*G_)))
                          + (size_t)lane * G_ + hcg;
        float4 gr = *(const float4*)gi;
        float4 gz = *(const float4*)(gi + 256);
        float4 gn = *(const float4*)(gi + 512);

        // gh = h @ W-slice
        ull a0=0,a1=0,a2=0,a3=0,a4=0,a5=0;
        const float* wk = WS + hc;
        const float* hk = HS + lane * HS_STRIDE;
#pragma unroll 4
        for (int kg = 0; kg < 64; kg++) {
            float4 h4 = *(const float4*)(hk + kg*4);
#pragma unroll
            for (int j = 0; j < 4; j++) {
                float hval = (j==0) ? h4.x : (j==1) ? h4.y : (j==2) ? h4.z : h4.w;
                ull av = splat2(hval);
                const float* wp = wk + (kg*4 + j)*96;
                ulonglong2 rr_ = *(const ulonglong2*)(wp);
                ulonglong2 zz_ = *(const ulonglong2*)(wp + 32);
                ulonglong2 nn_ = *(const ulonglong2*)(wp + 64);
                fma2(a0, av, rr_.x); fma2(a1, av, rr_.y);
                fma2(a2, av, zz_.x); fma2(a3, av, zz_.y);
                fma2(a4, av, nn_.x); fma2(a5, av, nn_.y);
            }
        }

        // fused GRU pointwise
        float2 r01 = unpack2(a0), r23 = unpack2(a1);
        float2 z01 = unpack2(a2), z23 = unpack2(a3);
        float2 n01 = unpack2(a4), n23 = unpack2(a5);

        const float* hkp = hk + hcg;
        float hp0 = hkp[0], hp1 = hkp[1], hp2 = hkp[2], hp3 = hkp[3];

        float r0 = sigm(gr.x + r01.x + br.x);
        float r1 = sigm(gr.y + r01.y + br.y);
        float r2 = sigm(gr.z + r23.x + br.z);
        float r3 = sigm(gr.w + r23.y + br.w);
        float z0 = sigm(gz.x + z01.x + bz.x);
        float z1 = sigm(gz.y + z01.y + bz.y);
        float z2 = sigm(gz.z + z23.x + bz.z);
        float z3 = sigm(gz.w + z23.y + bz.w);
        float n0 = tanh_(gn.x + r0 * (n01.x + bn.x));
        float n1 = tanh_(gn.y + r1 * (n01.y + bn.y));
        float n2 = tanh_(gn.z + r2 * (n23.x + bn.z));
        float n3 = tanh_(gn.w + r3 * (n23.y + bn.w));
        float4 hv;
        hv.x = (1.f - z0) * n0 + z0 * hp0;
        hv.y = (1.f - z1) * n1 + z1 * hp1;
        hv.z = (1.f - z2) * n2 + z2 * hp2;
        hv.w = (1.f - z3) * n3 + z3 * hp3;

        __stcg((float4*)(hdst + lane * 256 + hcg), hv);
        float* outp = isf ? (g_fwd + (size_t)s * (B_*H_))
                          : (g_rev + ((size_t)i * 64 + s) * (B_*H_));
        *(float4*)(outp + lane * 256 + hcg) = hv;

        // in-chain attention dot: this thread's 4-col contribution
        SB[w*32 + lane] = hv.x*wv.x + hv.y*wv.y + hv.z*wv.z + hv.w*wv.w;
        __syncthreads();
        if (w == 0) {
            float v = 0.f;
#pragma unroll
            for (int q = 0; q < 8; q++) v += SB[q*32 + lane];
            if (isf) g_scfp[(chunk*64 + s)*32 + lane] = v;
            else     g_scrp[(((size_t)chunk*64 + i)*64 + s)*32 + lane] = v;
        }

        if (s != len - 1) {
            asm volatile("barrier.cluster.arrive.aligned;" ::: "memory");
            asm volatile("barrier.cluster.wait.aligned;"   ::: "memory");
        }
    }
}

// ---------------- combine score partials + masked softmax -> alpha ----------
__global__ __launch_bounds__(256) void combine_softmax(
    const float* __restrict__ attn_b)
{
    const int i = blockIdx.x;
    __shared__ float sc[T_*B_];
    const float ab = attn_b[0];
    for (int idx = threadIdx.x; idx < (i+1)*32; idx += 256) {
        int t = idx >> 5, b = idx & 31;
        float v = ab;
#pragma unroll
        for (int c = 0; c < 8; c++) {
            v += g_scrp[(((size_t)c*64 + i)*64 + t)*32 + b];
            v += g_scfp[(c*64 + t)*32 + b];
        }
        sc[t*32 + b] = v;
    }
    __syncthreads();
    if (threadIdx.x < 32) {
        const int b = threadIdx.x;
        float m = -1e30f;
        for (int t = 0; t <= i; t++) m = fmaxf(m, sc[t*32 + b]);
        float ssum = 0.f;
        for (int t = 0; t <= i; t++) {
            float e = ex2f_(1.4426950408889634f * (sc[t*32 + b] - m));
            sc[t*32 + b] = e;
            ssum += e;
        }
        float inv = 1.f / ssum;
        for (int t = 0; t <= i; t++)
            g_sc[(i*64 + t)*32 + b] = sc[t*32 + b] * inv;
    }
}

// ---------------- context + concat ----------------
__global__ __launch_bounds__(256) void context_k() {
    const int i = blockIdx.x, bg = blockIdx.y;
    const int h = threadIdx.x;
    float accf[8], accr[8];
#pragma unroll
    for (int j = 0; j < 8; j++) { accf[j] = 0.f; accr[j] = 0.f; }
    for (int t = 0; t <= i; t++) {
        const float* al = g_sc + (i*64 + t)*32 + bg*8;
        const float* fr = g_fwd + ((size_t)(t*32 + bg*8)) * 256 + h;
        const float* rr = g_rev + ((size_t)((i*64 + t)*32 + bg*8)) * 256 + h;
#pragma unroll
        for (int j = 0; j < 8; j++) {
            float a = al[j];
            accf[j] += a * fr[(size_t)j*256];
            accr[j] += a * rr[(size_t)j*256];
        }
    }
    float inv = 1.f / (float)(i + 1);
#pragma unroll
    for (int j = 0; j < 8; j++) {
        int b = bg*8 + j;
        size_t row = (size_t)(i*32 + b);
        g_ht[row*1024 + h]       = accf[j] * inv;
        g_ht[row*1024 + 256 + h] = accr[j] * inv;
        g_ht[row*1024 + 512 + h] = g_fwd[((size_t)(i*32 + b))*256 + h];
        g_ht[row*1024 + 768 + h] = g_rev[((size_t)((i*64 + i)*32 + b))*256 + h];
    }
}

// ---------------- launch ----------------
extern "C" void kernel_launch(void* const* d_in, const int* in_sizes, int n_in,
                              void* d_out, int out_size)
{
    const float* x      = (const float*)d_in[0];
    const float* W_emb  = (const float*)d_in[1];
    const float* b_emb  = (const float*)d_in[2];
    const float* Wih_f  = (const float*)d_in[3];
    const float* Whh_f  = (const float*)d_in[4];
    const float* bih_f  = (const float*)d_in[5];
    const float* bhh_f  = (const float*)d_in[6];
    const float* Wih_r  = (const float*)d_in[7];
    const float* Whh_r  = (const float*)d_in[8];
    const float* bih_r  = (const float*)d_in[9];
    const float* bhh_r  = (const float*)d_in[10];
    const float* attn_w = (const float*)d_in[11];
    const float* attn_b = (const float*)d_in[12];
    const float* W_ao   = (const float*)d_in[13];
    const float* b_ao   = (const float*)d_in[14];
    const float* W_o    = (const float*)d_in[15];
    const float* b_o    = (const float*)d_in[16];
    float* out = (float*)d_out;

    void *p_day, *p_ht, *p_hto;
    cudaGetSymbolAddress(&p_day, g_day);
    cudaGetSymbolAddress(&p_ht,  g_ht);
    cudaGetSymbolAddress(&p_hto, g_hto);

    const int RNN_SMEM = (24576 + 32*HS_STRIDE + 8*32) * 4;
    cudaFuncSetAttribute(chain_rnn, cudaFuncAttributeMaxDynamicSharedMemorySize, RNN_SMEM);

    // 0: embedding GEMM
    gemm_v2<false><<<dim3(4, 64), 256>>>(x, W_emb, b_emb, (float*)p_day, M_, DD_, DIN_);
    // 1: fused gi GEMMs + zero state/partials
    gi_fused<<<dim3(12, 64, 2), 256>>>(Wih_f, bih_f, Wih_r, bih_r);
    // 2: recurrence (profiled slot)
    chain_rnn<<<NCHAIN*CLSZ, 256, RNN_SMEM>>>(Whh_f, Whh_r, bhh_f, bhh_r, attn_w);
    // 3: scores combine + softmax
    combine_softmax<<<64, 256>>>(attn_b);
    // 4: context + concat
    context_k<<<dim3(64, 4), 256>>>();
    // 5-6: output GEMMs
    gemm_v2<false><<<dim3(4, 64), 256>>>((const float*)p_ht, W_ao, b_ao, (float*)p_hto, M_, DD_, 4*H_);
    gemm_v2<true><<<dim3(15, 64), 256>>>((const float*)p_hto, W_o, b_o, out, M_, DOUT_, DD_);
}

// round 6
// speedup vs baseline: 1.1459x; 1.0001x over previous
#include <cuda_runtime.h>
#include <math.h>

typedef unsigned long long ull;

#define T_   64
#define B_   32
#define H_   256
#define G_   768
#define DD_  256
#define DIN_ 4096
#define DOUT_ 942
#define M_   (T_*B_)

#define NCHAIN 65
#define CLSZ   8
#define HS_STRIDE 260      // %32 == 4 -> conflict-free float4 LDS/STS

// ---------------- device scratch (static; no allocations) ----------------
__device__ float g_day [M_*DD_];
__device__ float g_gif [M_*G_];
__device__ float g_gir [M_*G_];
__device__ float g_hA  [NCHAIN*B_*H_];
__device__ float g_hB  [NCHAIN*B_*H_];
__device__ float g_fwd [T_*B_*H_];
__device__ float g_rev [T_*T_*B_*H_];       // [i][t][b][h], t<=i valid
__device__ float g_scrp[8*T_*T_*B_];        // rev score partials [chunk][i][t][b]
__device__ float g_scfp[8*T_*B_];           // fwd score partials [chunk][t][b]
__device__ float g_sc  [T_*T_*B_];          // alpha [i][t][b]
__device__ float g_ht  [M_*4*H_];
__device__ float g_hto [M_*DD_];

#define ZHA  (NCHAIN*B_*H_)                 // 532480
#define ZRP  (8*T_*T_*B_)                   // 1048576
#define ZFP  (8*T_*B_)                      // 16384
#define ZTOT (ZHA+ZRP+ZFP)

// ---------------- math helpers ----------------
__device__ __forceinline__ ull splat2(float x) {
    ull r; asm("mov.b64 %0,{%1,%1};" : "=l"(r) : "f"(x)); return r;
}
__device__ __forceinline__ void fma2(ull& c, ull a, ull b) {
    asm("fma.rn.f32x2 %0,%1,%2,%0;" : "+l"(c) : "l"(a), "l"(b));
}
__device__ __forceinline__ float2 unpack2(ull v) {
    float2 r; asm("mov.b64 {%0,%1},%2;" : "=f"(r.x), "=f"(r.y) : "l"(v)); return r;
}
__device__ __forceinline__ float ex2f_(float x) {
    float y; asm("ex2.approx.f32 %0,%1;" : "=f"(y) : "f"(x)); return y;
}
__device__ __forceinline__ float rcpf_(float x) {
    float y; asm("rcp.approx.f32 %0,%1;" : "=f"(y) : "f"(x)); return y;
}
__device__ __forceinline__ float sigm(float x) {
    return rcpf_(1.f + ex2f_(-1.4426950408889634f * x));
}
__device__ __forceinline__ float tanh_(float x) {
    return fmaf(-2.f, rcpf_(1.f + ex2f_(2.8853900817779268f * x)), 1.f);
}

// ---------------- GEMM core: C[M,N] = A[M,K] @ B[N,K]^T + bias ----------------
template<bool SIG>
__device__ __forceinline__ void gemm_body(
    const float* __restrict__ A, const float* __restrict__ Bm,
    const float* __restrict__ bias, float* __restrict__ C,
    int M, int N, int K, int m0, int n0,
    float* As, float* Bs)
{
    const int tid  = threadIdx.x;
    const int lane = tid & 31;
    const int w    = tid >> 5;

    const int arow = tid >> 3, ak = (tid & 7) * 4;
    const int bcol = tid >> 2, bk = (tid & 3) * 4;
    const bool bvalid = (n0 + bcol) < N;
    const float* Aptr = A + (size_t)(m0 + arow) * K + ak;
    const float* Bptr = Bm + (size_t)(n0 + bcol) * K + bk;

    float4 pa = *(const float4*)Aptr;
    float4 pb0 = bvalid ? *(const float4*)(Bptr)      : make_float4(0,0,0,0);
    float4 pb1 = bvalid ? *(const float4*)(Bptr + 16) : make_float4(0,0,0,0);

    ull acc[4] = {0ull, 0ull, 0ull, 0ull};

    for (int k0 = 0; k0 < K; k0 += 32) {
        __syncthreads();
        As[(ak+0)*33 + arow] = pa.x;
        As[(ak+1)*33 + arow] = pa.y;
        As[(ak+2)*33 + arow] = pa.z;
        As[(ak+3)*33 + arow] = pa.w;
        Bs[(bk+0)*68 + bcol] = pb0.x;
        Bs[(bk+1)*68 + bcol] = pb0.y;
        Bs[(bk+2)*68 + bcol] = pb0.z;
        Bs[(bk+3)*68 + bcol] = pb0.w;
        Bs[(bk+16)*68 + bcol] = pb1.x;
        Bs[(bk+17)*68 + bcol] = pb1.y;
        Bs[(bk+18)*68 + bcol] = pb1.z;
        Bs[(bk+19)*68 + bcol] = pb1.w;
        __syncthreads();

        if (k0 + 32 < K) {
            pa = *(const float4*)(Aptr + k0 + 32);
            if (bvalid) {
                pb0 = *(const float4*)(Bptr + k0 + 32);
                pb1 = *(const float4*)(Bptr + k0 + 48);
            }
        }
#pragma unroll 8
        for (int kk = 0; kk < 32; kk++) {
            ull av = splat2(As[kk*33 + lane]);
            ulonglong2 L0 = *(const ulonglong2*)&Bs[kk*68 + (w<<3)];
            ulonglong2 L1 = *(const ulonglong2*)&Bs[kk*68 + (w<<3) + 4];
            fma2(acc[0], av, L0.x);
            fma2(acc[1], av, L0.y);
            fma2(acc[2], av, L1.x);
            fma2(acc[3], av, L1.y);
        }
    }

    const int row = m0 + lane;
#pragma unroll
    for (int p = 0; p < 4; p++) {
        int col = n0 + (w<<3) + 2*p;
        float2 v = unpack2(acc[p]);
        if (col + 1 < N) {
            v.x += bias[col]; v.y += bias[col+1];
            if (SIG) { v.x = sigm(v.x); v.y = sigm(v.y); }
            *(float2*)(C + (size_t)row * N + col) = v;
        } else if (col < N) {
            v.x += bias[col];
            if (SIG) v.x = sigm(v.x);
            C[(size_t)row * N + col] = v.x;
        }
    }
}

template<bool SIG>
__global__ __launch_bounds__(256) void gemm_v2(
    const float* __restrict__ A, const float* __restrict__ Bm,
    const float* __restrict__ bias, float* __restrict__ C,
    int M, int N, int K)
{
    __shared__ float As[32*33];
    __shared__ float Bs[32*68];
    gemm_body<SIG>(A, Bm, bias, C, M, N, K, blockIdx.y*32, blockIdx.x*64, As, Bs);
}

// gi fused GEMM (z=0: fwd weights, z=1: rev) + zero-state prologue
__global__ __launch_bounds__(256) void gi_fused(
    const float* __restrict__ Wih_f, const float* __restrict__ bih_f,
    const float* __restrict__ Wih_r, const float* __restrict__ bih_r)
{
    __shared__ float As[32*33];
    __shared__ float Bs[32*68];

    // zero prologue: 1536 blocks cover ZTOT floats
    {
        int flat = blockIdx.x + 12*(blockIdx.y + 64*blockIdx.z);
        const int per = (ZTOT + 1535) / 1536;     // 1040
        int base = flat * per;
        int end  = base + per; if (end > ZTOT) end = ZTOT;
        for (int j = base + threadIdx.x; j < end; j += 256) {
            if (j < ZHA)            g_hA[j] = 0.f;
            else if (j < ZHA+ZRP)   g_scrp[j - ZHA] = 0.f;
            else                    g_scfp[j - ZHA - ZRP] = 0.f;
        }
    }

    const bool r = (blockIdx.z == 1);
    gemm_body<false>(g_day, r ? Wih_r : Wih_f, r ? bih_r : bih_f,
                     r ? g_gir : g_gif, M_, G_, DD_,
                     blockIdx.y*32, blockIdx.x*64, As, Bs);
}

// ---------------- per-chain cluster recurrence (+ in-chain attention dots) --
// 520 blocks = 65 clusters of 8. cidx 0 -> fwd chain (len 64); cidx>=1 ->
// rev chain i = 64-cidx (len i+1). Block = one 32-col h chunk.
__global__ __launch_bounds__(256) __cluster_dims__(CLSZ, 1, 1)
void chain_rnn(const float* __restrict__ Whh_f, const float* __restrict__ Whh_r,
               const float* __restrict__ bhh_f, const float* __restrict__ bhh_r,
               const float* __restrict__ attn_w)
{
    extern __shared__ float sm[];
    float* WS = sm;                       // 96 x 256: 24576 floats
    float* HS = sm + 24576;               // 32 x HS_STRIDE
    float* SB = sm + 24576 + 32*HS_STRIDE; // 8 x 32 score partials

    const int tid   = threadIdx.x;
    const int lane  = tid & 31;
    const int w     = tid >> 5;
    const int cidx  = blockIdx.x >> 3;
    const int chunk = blockIdx.x & 7;
    const int c0    = chunk * 32;

    const bool isf = (cidx == 0);
    const int i    = 64 - cidx;
    const int len  = isf ? 64 : (i + 1);

    const float* Wg   = isf ? Whh_f : Whh_r;
    const float* bias = isf ? bhh_f : bhh_r;

    // stage W slice once (gate rows r[0..31], z[32..63], n[64..95])
    for (int idx = tid; idx < 96*64; idx += 256) {
        int row = idx % 96;
        int k4  = (idx / 96) * 4;
        int grow = (row >> 5) * 256 + c0 + (row & 31);
        float4 v = *(const float4*)(Wg + (size_t)grow * 256 + k4);
        WS[(k4+0)*96 + row] = v.x;
        WS[(k4+1)*96 + row] = v.y;
        WS[(k4+2)*96 + row] = v.z;
        WS[(k4+3)*96 + row] = v.w;
    }

    const int hc  = w << 2;
    const int hcg = c0 + hc;
    const float4 br = *(const float4*)(bias + hcg);
    const float4 bz = *(const float4*)(bias + 256 + hcg);
    const float4 bn = *(const float4*)(bias + 512 + hcg);
    const float4 wv = *(const float4*)(attn_w + (isf ? 0 : 256) + hcg);

    float* bufA = g_hA + (size_t)cidx * (B_*H_);
    float* bufB = g_hB + (size_t)cidx * (B_*H_);

    const int srow = tid >> 3;
    const int skb  = (tid & 7) * 4;

    __syncthreads();

    for (int s = 0; s < len; s++) {
        float* hsrc = (s & 1) ? bufB : bufA;
        float* hdst = (s & 1) ? bufA : bufB;

        // stage h (32x256) via float4, conflict-free
        {
            const float* src = hsrc + srow * 256 + skb;
            float* d = HS + srow * HS_STRIDE + skb;
#pragma unroll
            for (int q = 0; q < 8; q++)
                *(float4*)(d + q*32) = __ldcg((const float4*)(src + q * 32));
        }
        __syncthreads();

        // gi loads early (hidden under gemm)
        const float* gi = (isf ? (g_gif + (size_t)s * (B_*G_))
                               : (g_gir + (size_t)(i - s) * (B_*G_)))
                          + (size_t)lane * G_ + hcg;
        float4 gr = *(const float4*)gi;
        float4 gz = *(const float4*)(gi + 256);
        float4 gn = *(const float4*)(gi + 512);

        // gh = h @ W-slice
        ull a0=0,a1=0,a2=0,a3=0,a4=0,a5=0;
        const float* wk = WS + hc;
        const float* hk = HS + lane * HS_STRIDE;
#pragma unroll 4
        for (int kg = 0; kg < 64; kg++) {
            float4 h4 = *(const float4*)(hk + kg*4);
#pragma unroll
            for (int j = 0; j < 4; j++) {
                float hval = (j==0) ? h4.x : (j==1) ? h4.y : (j==2) ? h4.z : h4.w;
                ull av = splat2(hval);
                const float* wp = wk + (kg*4 + j)*96;
                ulonglong2 rr_ = *(const ulonglong2*)(wp);
                ulonglong2 zz_ = *(const ulonglong2*)(wp + 32);
                ulonglong2 nn_ = *(const ulonglong2*)(wp + 64);
                fma2(a0, av, rr_.x); fma2(a1, av, rr_.y);
                fma2(a2, av, zz_.x); fma2(a3, av, zz_.y);
                fma2(a4, av, nn_.x); fma2(a5, av, nn_.y);
            }
        }

        // fused GRU pointwise
        float2 r01 = unpack2(a0), r23 = unpack2(a1);
        float2 z01 = unpack2(a2), z23 = unpack2(a3);
        float2 n01 = unpack2(a4), n23 = unpack2(a5);

        const float* hkp = hk + hcg;
        float hp0 = hkp[0], hp1 = hkp[1], hp2 = hkp[2], hp3 = hkp[3];

        float r0 = sigm(gr.x + r01.x + br.x);
        float r1 = sigm(gr.y + r01.y + br.y);
        float r2 = sigm(gr.z + r23.x + br.z);
        float r3 = sigm(gr.w + r23.y + br.w);
        float z0 = sigm(gz.x + z01.x + bz.x);
        float z1 = sigm(gz.y + z01.y + bz.y);
        float z2 = sigm(gz.z + z23.x + bz.z);
        float z3 = sigm(gz.w + z23.y + bz.w);
        float n0 = tanh_(gn.x + r0 * (n01.x + bn.x));
        float n1 = tanh_(gn.y + r1 * (n01.y + bn.y));
        float n2 = tanh_(gn.z + r2 * (n23.x + bn.z));
        float n3 = tanh_(gn.w + r3 * (n23.y + bn.w));
        float4 hv;
        hv.x = (1.f - z0) * n0 + z0 * hp0;
        hv.y = (1.f - z1) * n1 + z1 * hp1;
        hv.z = (1.f - z2) * n2 + z2 * hp2;
        hv.w = (1.f - z3) * n3 + z3 * hp3;

        __stcg((float4*)(hdst + lane * 256 + hcg), hv);
        float* outp = isf ? (g_fwd + (size_t)s * (B_*H_))
                          : (g_rev + ((size_t)i * 64 + s) * (B_*H_));
        *(float4*)(outp + lane * 256 + hcg) = hv;

        // in-chain attention dot: this thread's 4-col contribution
        SB[w*32 + lane] = hv.x*wv.x + hv.y*wv.y + hv.z*wv.z + hv.w*wv.w;
        __syncthreads();
        if (w == 0) {
            float v = 0.f;
#pragma unroll
            for (int q = 0; q < 8; q++) v += SB[q*32 + lane];
            if (isf) g_scfp[(chunk*64 + s)*32 + lane] = v;
            else     g_scrp[(((size_t)chunk*64 + i)*64 + s)*32 + lane] = v;
        }

        if (s != len - 1) {
            asm volatile("barrier.cluster.arrive.aligned;" ::: "memory");
            asm volatile("barrier.cluster.wait.aligned;"   ::: "memory");
        }
    }
}

// ---------------- combine score partials + masked softmax -> alpha ----------
__global__ __launch_bounds__(256) void combine_softmax(
    const float* __restrict__ attn_b)
{
    const int i = blockIdx.x;
    __shared__ float sc[T_*B_];
    const float ab = attn_b[0];
    for (int idx = threadIdx.x; idx < (i+1)*32; idx += 256) {
        int t = idx >> 5, b = idx & 31;
        float v = ab;
#pragma unroll
        for (int c = 0; c < 8; c++) {
            v += g_scrp[(((size_t)c*64 + i)*64 + t)*32 + b];
            v += g_scfp[(c*64 + t)*32 + b];
        }
        sc[t*32 + b] = v;
    }
    __syncthreads();
    if (threadIdx.x < 32) {
        const int b = threadIdx.x;
        float m = -1e30f;
        for (int t = 0; t <= i; t++) m = fmaxf(m, sc[t*32 + b]);
        float ssum = 0.f;
        for (int t = 0; t <= i; t++) {
            float e = ex2f_(1.4426950408889634f * (sc[t*32 + b] - m));
            sc[t*32 + b] = e;
            ssum += e;
        }
        float inv = 1.f / ssum;
        for (int t = 0; t <= i; t++)
            g_sc[(i*64 + t)*32 + b] = sc[t*32 + b] * inv;
    }
}

// ---------------- context + concat ----------------
__global__ __launch_bounds__(256) void context_k() {
    const int i = blockIdx.x, bg = blockIdx.y;
    const int h = threadIdx.x;
    float accf[8], accr[8];
#pragma unroll
    for (int j = 0; j < 8; j++) { accf[j] = 0.f; accr[j] = 0.f; }
    for (int t = 0; t <= i; t++) {
        const float* al = g_sc + (i*64 + t)*32 + bg*8;
        const float* fr = g_fwd + ((size_t)(t*32 + bg*8)) * 256 + h;
        const float* rr = g_rev + ((size_t)((i*64 + t)*32 + bg*8)) * 256 + h;
#pragma unroll
        for (int j = 0; j < 8; j++) {
            float a = al[j];
            accf[j] += a * fr[(size_t)j*256];
            accr[j] += a * rr[(size_t)j*256];
        }
    }
    float inv = 1.f / (float)(i + 1);
#pragma unroll
    for (int j = 0; j < 8; j++) {
        int b = bg*8 + j;
        size_t row = (size_t)(i*32 + b);
        g_ht[row*1024 + h]       = accf[j] * inv;
        g_ht[row*1024 + 256 + h] = accr[j] * inv;
        g_ht[row*1024 + 512 + h] = g_fwd[((size_t)(i*32 + b))*256 + h];
        g_ht[row*1024 + 768 + h] = g_rev[((size_t)((i*64 + i)*32 + b))*256 + h];
    }
}

// ---------------- launch ----------------
extern "C" void kernel_launch(void* const* d_in, const int* in_sizes, int n_in,
                              void* d_out, int out_size)
{
    const float* x      = (const float*)d_in[0];
    const float* W_emb  = (const float*)d_in[1];
    const float* b_emb  = (const float*)d_in[2];
    const float* Wih_f  = (const float*)d_in[3];
    const float* Whh_f  = (const float*)d_in[4];
    const float* bih_f  = (const float*)d_in[5];
    const float* bhh_f  = (const float*)d_in[6];
    const float* Wih_r  = (const float*)d_in[7];
    const float* Whh_r  = (const float*)d_in[8];
    const float* bih_r  = (const float*)d_in[9];
    const float* bhh_r  = (const float*)d_in[10];
    const float* attn_w = (const float*)d_in[11];
    const float* attn_b = (const float*)d_in[12];
    const float* W_ao   = (const float*)d_in[13];
    const float* b_ao   = (const float*)d_in[14];
    const float* W_o    = (const float*)d_in[15];
    const float* b_o    = (const float*)d_in[16];
    float* out = (float*)d_out;

    void *p_day, *p_ht, *p_hto;
    cudaGetSymbolAddress(&p_day, g_day);
    cudaGetSymbolAddress(&p_ht,  g_ht);
    cudaGetSymbolAddress(&p_hto, g_hto);

    const int RNN_SMEM = (24576 + 32*HS_STRIDE + 8*32) * 4;
    cudaFuncSetAttribute(chain_rnn, cudaFuncAttributeMaxDynamicSharedMemorySize, RNN_SMEM);

    // 0: embedding GEMM
    gemm_v2<false><<<dim3(4, 64), 256>>>(x, W_emb, b_emb, (float*)p_day, M_, DD_, DIN_);
    // 1: fused gi GEMMs + zero state/partials
    gi_fused<<<dim3(12, 64, 2), 256>>>(Wih_f, bih_f, Wih_r, bih_r);
    // 2: recurrence (profiled slot)
    chain_rnn<<<NCHAIN*CLSZ, 256, RNN_SMEM>>>(Whh_f, Whh_r, bhh_f, bhh_r, attn_w);
    // 3: scores combine + softmax
    combine_softmax<<<64, 256>>>(attn_b);
    // 4: context + concat
    context_k<<<dim3(64, 4), 256>>>();
    // 5-6: output GEMMs
    gemm_v2<false><<<dim3(4, 64), 256>>>((const float*)p_ht, W_ao, b_ao, (float*)p_hto, M_, DD_, 4*H_);
    gemm_v2<true><<<dim3(15, 64), 256>>>((const float*)p_hto, W_o, b_o, out, M_, DOUT_, DD_);
}

// round 8
// speedup vs baseline: 1.6195x; 1.4133x over previous
#include <cuda_runtime.h>
#include <math.h>

typedef unsigned long long ull;

#define T_   64
#define B_   32
#define H_   256
#define G_   768
#define DD_  256
#define DIN_ 4096
#define DOUT_ 942
#define M_   (T_*B_)
#define HSTR 260

__device__ float g_day [M_*DD_];
__device__ float g_gif [M_*G_];
__device__ float g_gir [M_*G_];
__device__ float g_hA  [65*B_*H_];
__device__ float g_hB  [65*B_*H_];
__device__ float g_fwd [T_*B_*H_];
__device__ float g_rev [T_*T_*B_*H_];
__device__ float g_scrp[8*T_*T_*B_];
__device__ float g_scfp[8*T_*B_];
__device__ float g_sc  [T_*T_*B_];
__device__ float g_ht  [M_*4*H_];
__device__ float g_hto [M_*DD_];

#define ZHA (65*B_*H_)
#define ZRP (8*T_*T_*B_)
#define ZFP (8*T_*B_)
#define ZTOT (ZHA+ZRP+ZFP)

__device__ __forceinline__ ull splat2(float x){ull r;asm("mov.b64 %0,{%1,%1};":"=l"(r):"f"(x));return r;}
__device__ __forceinline__ void fma2(ull&c,ull a,ull b){asm("fma.rn.f32x2 %0,%1,%2,%0;":"+l"(c):"l"(a),"l"(b));}
__device__ __forceinline__ float2 unpack2(ull v){float2 r;asm("mov.b64 {%0,%1},%2;":"=f"(r.x),"=f"(r.y):"l"(v));return r;}
__device__ __forceinline__ float ex2f_(float x){float y;asm("ex2.approx.f32 %0,%1;":"=f"(y):"f"(x));return y;}
__device__ __forceinline__ float rcpf_(float x){float y;asm("rcp.approx.f32 %0,%1;":"=f"(y):"f"(x));return y;}
__device__ __forceinline__ float sigm(float x){return rcpf_(1.f+ex2f_(-1.4426950408889634f*x));}
__device__ __forceinline__ float tanh_(float x){return fmaf(-2.f,rcpf_(1.f+ex2f_(2.8853900817779268f*x)),1.f);}

__global__ void zero_k() {
    for (int j = blockIdx.x*256 + threadIdx.x; j < ZTOT; j += gridDim.x*256) {
        if (j < ZHA) g_hA[j] = 0.f;
        else if (j < ZHA+ZRP) g_scrp[j-ZHA] = 0.f;
        else g_scfp[j-ZHA-ZRP] = 0.f;
    }
}

// ---------------- GEMM: C[M,N] = A[M,K] @ B[N,K]^T + bias ----------------
template<bool SIG>
__device__ __forceinline__ void gemm_body(
    const float* __restrict__ A, const float* __restrict__ Bm,
    const float* __restrict__ bias, float* __restrict__ C,
    int N, int K, int m0, int n0, float* As, float* Bs)
{
    const int tid = threadIdx.x, lane = tid & 31, w = tid >> 5;
    const int arow = tid >> 3, ak = (tid & 7)*4;
    const int bcol = tid >> 2, bk = (tid & 3)*4;
    const bool bvalid = (n0 + bcol) < N;
    const float* Aptr = A + (size_t)(m0+arow)*K + ak;
    const float* Bptr = Bm + (size_t)(n0+bcol)*K + bk;
    float4 pa = *(const float4*)Aptr;
    float4 pb0 = bvalid ? *(const float4*)(Bptr) : make_float4(0,0,0,0);
    float4 pb1 = bvalid ? *(const float4*)(Bptr+16) : make_float4(0,0,0,0);
    ull acc[4] = {0,0,0,0};
    for (int k0 = 0; k0 < K; k0 += 32) {
        __syncthreads();
        As[(ak+0)*33+arow]=pa.x; As[(ak+1)*33+arow]=pa.y;
        As[(ak+2)*33+arow]=pa.z; As[(ak+3)*33+arow]=pa.w;
        Bs[(bk+0)*68+bcol]=pb0.x; Bs[(bk+1)*68+bcol]=pb0.y;
        Bs[(bk+2)*68+bcol]=pb0.z; Bs[(bk+3)*68+bcol]=pb0.w;
        Bs[(bk+16)*68+bcol]=pb1.x; Bs[(bk+17)*68+bcol]=pb1.y;
        Bs[(bk+18)*68+bcol]=pb1.z; Bs[(bk+19)*68+bcol]=pb1.w;
        __syncthreads();
        if (k0+32 < K) {
            pa = *(const float4*)(Aptr+k0+32);
            if (bvalid) { pb0 = *(const float4*)(Bptr+k0+32); pb1 = *(const float4*)(Bptr+k0+48); }
        }
#pragma unroll 8
        for (int kk = 0; kk < 32; kk++) {
            ull av = splat2(As[kk*33+lane]);
            ulonglong2 L0 = *(const ulonglong2*)&Bs[kk*68+(w<<3)];
            ulonglong2 L1 = *(const ulonglong2*)&Bs[kk*68+(w<<3)+4];
            fma2(acc[0],av,L0.x); fma2(acc[1],av,L0.y);
            fma2(acc[2],av,L1.x); fma2(acc[3],av,L1.y);
        }
    }
    const int row = m0 + lane;
#pragma unroll
    for (int p = 0; p < 4; p++) {
        int col = n0 + (w<<3) + 2*p;
        float2 v = unpack2(acc[p]);
        if (col+1 < N) {
            v.x += bias[col]; v.y += bias[col+1];
            if (SIG) { v.x = sigm(v.x); v.y = sigm(v.y); }
            *(float2*)(C + (size_t)row*N + col) = v;
        } else if (col < N) {
            v.x += bias[col]; if (SIG) v.x = sigm(v.x);
            C[(size_t)row*N + col] = v.x;
        }
    }
}

template<bool SIG>
__global__ __launch_bounds__(256) void gemm_v2(
    const float* __restrict__ A, const float* __restrict__ Bm,
    const float* __restrict__ bias, float* __restrict__ C, int N, int K)
{
    __shared__ float As[32*33]; __shared__ float Bs[32*68];
    gemm_body<SIG>(A, Bm, bias, C, N, K, blockIdx.y*32, blockIdx.x*64, As, Bs);
}

__global__ __launch_bounds__(256) void gi_fused(
    const float* __restrict__ Wih_f, const float* __restrict__ bih_f,
    const float* __restrict__ Wih_r, const float* __restrict__ bih_r)
{
    __shared__ float As[32*33]; __shared__ float Bs[32*68];
    const bool r = (blockIdx.z == 1);
    gemm_body<false>(g_day, r?Wih_r:Wih_f, r?bih_r:bih_f, r?g_gir:g_gif,
                     G_, DD_, blockIdx.y*32, blockIdx.x*64, As, Bs);
}

// ---------------- paired-chain cluster recurrence ----------------
// 264 blocks = 33 groups x 8 chunks, cluster 8. group 0: fwd chain alone
// (state slot 64). group g>=1: rev chains iA=65-2g (63..1) and iB=64-2g
// (62..0), sharing the Whh_r smem slice. Block owns h-cols [chunk*32,+32).
__global__ __launch_bounds__(256) __cluster_dims__(8,1,1)
void chain_rnn(const float* __restrict__ Whh_f, const float* __restrict__ Whh_r,
               const float* __restrict__ bhh_f, const float* __restrict__ bhh_r,
               const float* __restrict__ attn_w)
{
    extern __shared__ float sm[];
    float* WS  = sm;                 // 96x256 = 24576
    float* HSA = sm + 24576;         // 32*HSTR
    float* HSB = HSA + 32*HSTR;
    float* SBA = HSB + 32*HSTR;      // 256
    float* SBB = SBA + 256;          // 256

    const int tid = threadIdx.x, lane = tid & 31, w = tid >> 5;
    const int grp = blockIdx.x >> 3, chunk = blockIdx.x & 7, c0 = chunk*32;
    const bool isf = (grp == 0);
    const int iA = 65 - 2*grp;            // 63..1 for grp 1..32
    const int iB = 64 - 2*grp;            // 62..0
    const int lenA = isf ? 64 : (iA + 1);
    const int lenB = iB + 1;
    const int slotA = isf ? 64 : iA;

    const float* Wg   = isf ? Whh_f : Whh_r;
    const float* bias = isf ? bhh_f : bhh_r;

    for (int idx = tid; idx < 96*64; idx += 256) {
        int row = idx % 96, k4 = (idx/96)*4;
        int grow = (row>>5)*256 + c0 + (row&31);
        float4 v = *(const float4*)(Wg + (size_t)grow*256 + k4);
        WS[(k4+0)*96+row]=v.x; WS[(k4+1)*96+row]=v.y;
        WS[(k4+2)*96+row]=v.z; WS[(k4+3)*96+row]=v.w;
    }

    const int hc = w<<2, hcg = c0 + hc;
    const float4 br = *(const float4*)(bias + hcg);
    const float4 bz = *(const float4*)(bias + 256 + hcg);
    const float4 bn = *(const float4*)(bias + 512 + hcg);
    const float4 wvA = *(const float4*)(attn_w + (isf?0:256) + hcg);
    const float4 wvB = *(const float4*)(attn_w + 256 + hcg);

    float* bA0 = g_hA + (size_t)slotA*(B_*H_);
    float* bA1 = g_hB + (size_t)slotA*(B_*H_);
    float* bB0 = g_hA + (size_t)(iB < 0 ? 0 : iB)*(B_*H_);
    float* bB1 = g_hB + (size_t)(iB < 0 ? 0 : iB)*(B_*H_);

    const int srow = tid >> 3, skb = (tid & 7)*4;
    __syncthreads();

    for (int s = 0; s < lenA; s++) {
        float* hsrcA = (s&1) ? bA1 : bA0;  float* hdstA = (s&1) ? bA0 : bA1;
        float* hsrcB = (s&1) ? bB1 : bB0;  float* hdstB = (s&1) ? bB0 : bB1;
        const bool actB = !isf && (s < lenB);
        {
            const float* src = hsrcA + srow*256 + skb;
            float* d = HSA + srow*HSTR + skb;
#pragma unroll
            for (int q = 0; q < 8; q++) *(float4*)(d+q*32) = __ldcg((const float4*)(src+q*32));
            if (actB) {
                const float* sb = hsrcB + srow*256 + skb;
                float* db = HSB + srow*HSTR + skb;
#pragma unroll
                for (int q = 0; q < 8; q++) *(float4*)(db+q*32) = __ldcg((const float4*)(sb+q*32));
            }
        }
        __syncthreads();

        const float* giA = (isf ? (g_gif + (size_t)s*(B_*G_))
                                : (g_gir + (size_t)(iA-s)*(B_*G_))) + (size_t)lane*G_ + hcg;
        float4 grA = *(const float4*)giA;
        float4 gzA = *(const float4*)(giA+256);
        float4 gnA = *(const float4*)(giA+512);
        float4 grB, gzB, gnB;
        if (actB) {
            const float* giB = g_gir + (size_t)(iB-s)*(B_*G_) + (size_t)lane*G_ + hcg;
            grB = *(const float4*)giB; gzB = *(const float4*)(giB+256); gnB = *(const float4*)(giB+512);
        }

        ull aA[6] = {0,0,0,0,0,0}, aB[6] = {0,0,0,0,0,0};
        const float* wk = WS + hc;
        const float* hkA = HSA + lane*HSTR;
        const float* hkB = HSB + lane*HSTR;
        if (!isf) {
#pragma unroll 4
            for (int kq = 0; kq < 64; kq++) {
                float4 hA4 = *(const float4*)(hkA + kq*4);
                float4 hB4 = *(const float4*)(hkB + kq*4);
                const float* fA = (const float*)&hA4;
                const float* fB = (const float*)&hB4;
#pragma unroll
                for (int j = 0; j < 4; j++) {
                    const float* wp = wk + (kq*4+j)*96;
                    ulonglong2 rr = *(const ulonglong2*)(wp);
                    ulonglong2 zz = *(const ulonglong2*)(wp+32);
                    ulonglong2 nn = *(const ulonglong2*)(wp+64);
                    ull avA = splat2(fA[j]), avB = splat2(fB[j]);
                    fma2(aA[0],avA,rr.x); fma2(aA[1],avA,rr.y);
                    fma2(aA[2],avA,zz.x); fma2(aA[3],avA,zz.y);
                    fma2(aA[4],avA,nn.x); fma2(aA[5],avA,nn.y);
                    fma2(aB[0],avB,rr.x); fma2(aB[1],avB,rr.y);
                    fma2(aB[2],avB,zz.x); fma2(aB[3],avB,zz.y);
                    fma2(aB[4],avB,nn.x); fma2(aB[5],avB,nn.y);
                }
            }
        } else {
#pragma unroll 4
            for (int kq = 0; kq < 64; kq++) {
                float4 hA4 = *(const float4*)(hkA + kq*4);
                const float* fA = (const float*)&hA4;
#pragma unroll
                for (int j = 0; j < 4; j++) {
                    const float* wp = wk + (kq*4+j)*96;
                    ulonglong2 rr = *(const ulonglong2*)(wp);
                    ulonglong2 zz = *(const ulonglong2*)(wp+32);
                    ulonglong2 nn = *(const ulonglong2*)(wp+64);
                    ull avA = splat2(fA[j]);
                    fma2(aA[0],avA,rr.x); fma2(aA[1],avA,rr.y);
                    fma2(aA[2],avA,zz.x); fma2(aA[3],avA,zz.y);
                    fma2(aA[4],avA,nn.x); fma2(aA[5],avA,nn.y);
                }
            }
        }

        // pointwise A
        {
            float2 r01=unpack2(aA[0]), r23=unpack2(aA[1]);
            float2 z01=unpack2(aA[2]), z23=unpack2(aA[3]);
            float2 n01=unpack2(aA[4]), n23=unpack2(aA[5]);
            const float* hp_ = hkA + hcg;
            float r0=sigm(grA.x+r01.x+br.x), r1=sigm(grA.y+r01.y+br.y);
            float r2=sigm(grA.z+r23.x+br.z), r3=sigm(grA.w+r23.y+br.w);
            float z0=sigm(gzA.x+z01.x+bz.x), z1=sigm(gzA.y+z01.y+bz.y);
            float z2=sigm(gzA.z+z23.x+bz.z), z3=sigm(gzA.w+z23.y+bz.w);
            float n0=tanh_(gnA.x+r0*(n01.x+bn.x)), n1=tanh_(gnA.y+r1*(n01.y+bn.y));
            float n2=tanh_(gnA.z+r2*(n23.x+bn.z)), n3=tanh_(gnA.w+r3*(n23.y+bn.w));
            float4 hv;
            hv.x=(1.f-z0)*n0+z0*hp_[0]; hv.y=(1.f-z1)*n1+z1*hp_[1];
            hv.z=(1.f-z2)*n2+z2*hp_[2]; hv.w=(1.f-z3)*n3+z3*hp_[3];
            __stcg((float4*)(hdstA + lane*256 + hcg), hv);
            float* outp = isf ? (g_fwd + (size_t)s*(B_*H_))
                              : (g_rev + ((size_t)iA*64 + s)*(B_*H_));
            *(float4*)(outp + lane*256 + hcg) = hv;
            SBA[w*32+lane] = hv.x*wvA.x + hv.y*wvA.y + hv.z*wvA.z + hv.w*wvA.w;
        }
        // pointwise B
        if (actB) {
            float2 r01=unpack2(aB[0]), r23=unpack2(aB[1]);
            float2 z01=unpack2(aB[2]), z23=unpack2(aB[3]);
            float2 n01=unpack2(aB[4]), n23=unpack2(aB[5]);
            const float* hp_ = hkB + hcg;
            float r0=sigm(grB.x+r01.x+br.x), r1=sigm(grB.y+r01.y+br.y);
            float r2=sigm(grB.z+r23.x+br.z), r3=sigm(grB.w+r23.y+br.w);
            float z0=sigm(gzB.x+z01.x+bz.x), z1=sigm(gzB.y+z01.y+bz.y);
            float z2=sigm(gzB.z+z23.x+bz.z), z3=sigm(gzB.w+z23.y+bz.w);
            float n0=tanh_(gnB.x+r0*(n01.x+bn.x)), n1=tanh_(gnB.y+r1*(n01.y+bn.y));
            float n2=tanh_(gnB.z+r2*(n23.x+bn.z)), n3=tanh_(gnB.w+r3*(n23.y+bn.w));
            float4 hv;
            hv.x=(1.f-z0)*n0+z0*hp_[0]; hv.y=(1.f-z1)*n1+z1*hp_[1];
            hv.z=(1.f-z2)*n2+z2*hp_[2]; hv.w=(1.f-z3)*n3+z3*hp_[3];
            __stcg((float4*)(hdstB + lane*256 + hcg), hv);
            *(float4*)(g_rev + ((size_t)iB*64 + s)*(B_*H_) + lane*256 + hcg) = hv;
            SBB[w*32+lane] = hv.x*wvB.x + hv.y*wvB.y + hv.z*wvB.z + hv.w*wvB.w;
        }
        __syncthreads();
        if (w == 0) {
            float v = 0.f;
#pragma unroll
            for (int q = 0; q < 8; q++) v += SBA[q*32+lane];
            if (isf) g_scfp[(chunk*64+s)*32+lane] = v;
            else     g_scrp[(((size_t)chunk*64+iA)*64+s)*32+lane] = v;
        } else if (w == 1 && actB) {
            float v = 0.f;
#pragma unroll
            for (int q = 0; q < 8; q++) v += SBB[q*32+lane];
            g_scrp[(((size_t)chunk*64+iB)*64+s)*32+lane] = v;
        }
        if (s != lenA-1) {
            asm volatile("barrier.cluster.arrive.aligned;" ::: "memory");
            asm volatile("barrier.cluster.wait.aligned;"   ::: "memory");
        }
    }
}

__global__ __launch_bounds__(256) void combine_softmax(const float* __restrict__ attn_b) {
    const int i = blockIdx.x;
    __shared__ float sc[T_*B_];
    const float ab = attn_b[0];
    for (int idx = threadIdx.x; idx < (i+1)*32; idx += 256) {
        int t = idx >> 5, b = idx & 31;
        float v = ab;
#pragma unroll
        for (int c = 0; c < 8; c++) {
            v += g_scrp[(((size_t)c*64+i)*64+t)*32+b];
            v += g_scfp[(c*64+t)*32+b];
        }
        sc[t*32+b] = v;
    }
    __syncthreads();
    if (threadIdx.x < 32) {
        const int b = threadIdx.x;
        float m = -1e30f;
        for (int t = 0; t <= i; t++) m = fmaxf(m, sc[t*32+b]);
        float ssum = 0.f;
        for (int t = 0; t <= i; t++) {
            float e = ex2f_(1.4426950408889634f*(sc[t*32+b]-m));
            sc[t*32+b] = e; ssum += e;
        }
        float inv = 1.f/ssum;
        for (int t = 0; t <= i; t++) g_sc[(i*64+t)*32+b] = sc[t*32+b]*inv;
    }
}

__global__ __launch_bounds__(256) void context_k() {
    const int i = blockIdx.x, bg = blockIdx.y;
    const int h = threadIdx.x;
    float accf[8], accr[8];
#pragma unroll
    for (int j = 0; j < 8; j++) { accf[j]=0.f; accr[j]=0.f; }
    for (int t = 0; t <= i; t++) {
        const float* al = g_sc + (i*64+t)*32 + bg*8;
        const float* fr = g_fwd + ((size_t)(t*32+bg*8))*256 + h;
        const float* rr = g_rev + ((size_t)((i*64+t)*32+bg*8))*256 + h;
#pragma unroll
        for (int j = 0; j < 8; j++) {
            float a = al[j];
            accf[j] += a*fr[(size_t)j*256];
            accr[j] += a*rr[(size_t)j*256];
        }
    }
    float inv = 1.f/(float)(i+1);
#pragma unroll
    for (int j = 0; j < 8; j++) {
        int b = bg*8+j;
        size_t row = (size_t)(i*32+b);
        g_ht[row*1024 + h]       = accf[j]*inv;
        g_ht[row*1024 + 256 + h] = accr[j]*inv;
        g_ht[row*1024 + 512 + h] = g_fwd[((size_t)(i*32+b))*256 + h];
        g_ht[row*1024 + 768 + h] = g_rev[((size_t)((i*64+i)*32+b))*256 + h];
    }
}

extern "C" void kernel_launch(void* const* d_in, const int* in_sizes, int n_in,
                              void* d_out, int out_size)
{
    const float* x      = (const float*)d_in[0];
    const float* W_emb  = (const float*)d_in[1];
    const float* b_emb  = (const float*)d_in[2];
    const float* Wih_f  = (const float*)d_in[3];
    const float* Whh_f  = (const float*)d_in[4];
    const float* bih_f  = (const float*)d_in[5];
    const float* bhh_f  = (const float*)d_in[6];
    const float* Wih_r  = (const float*)d_in[7];
    const float* Whh_r  = (const float*)d_in[8];
    const float* bih_r  = (const float*)d_in[9];
    const float* bhh_r  = (const float*)d_in[10];
    const float* attn_w = (const float*)d_in[11];
    const float* attn_b = (const float*)d_in[12];
    const float* W_ao   = (const float*)d_in[13];
    const float* b_ao   = (const float*)d_in[14];
    const float* W_o    = (const float*)d_in[15];
    const float* b_o    = (const float*)d_in[16];
    float* out = (float*)d_out;

    void *p_day, *p_ht, *p_hto;
    cudaGetSymbolAddress(&p_day, g_day);
    cudaGetSymbolAddress(&p_ht,  g_ht);
    cudaGetSymbolAddress(&p_hto, g_hto);

    const int RNN_SMEM = (24576 + 2*32*HSTR + 512) * 4;  // 166912 B
    cudaFuncSetAttribute(chain_rnn, cudaFuncAttributeMaxDynamicSharedMemorySize, RNN_SMEM);

    zero_k<<<512, 256>>>();                                                   // 0
    gemm_v2<false><<<dim3(4, 64), 256>>>(x, W_emb, b_emb, (float*)p_day, DD_, DIN_);  // 1
    gi_fused<<<dim3(12, 64, 2), 256>>>(Wih_f, bih_f, Wih_r, bih_r);           // 2
    chain_rnn<<<264, 256, RNN_SMEM>>>(Whh_f, Whh_r, bhh_f, bhh_r, attn_w);    // 3 (profiled)
    combine_softmax<<<64, 256>>>(attn_b);                                     // 4
    context_k<<<dim3(64, 4), 256>>>();                                        // 5
    gemm_v2<false><<<dim3(4, 64), 256>>>((const float*)p_ht, W_ao, b_ao, (float*)p_hto, DD_, 4*H_); // 6
    gemm_v2<true><<<dim3(15, 64), 256>>>((const float*)p_hto, W_o, b_o, out, DOUT_, DD_);           // 7
}